// round 4
// baseline (speedup 1.0000x reference)
#include <cuda_runtime.h>
#include <cuda_bf16.h>
#include <cstddef>

// Problem constants
#define BB 2
#define NN 1569
#define CC 768
#define HH 12
#define DD 64
#define FF 8
#define PP 196
#define SS 1568        // F*P
#define BH 24          // B*H
#define SCALE 0.125f   // d^-0.5

// ---------------- scratch (device globals; no allocation) ----------------
__device__ float g_qkv  [(size_t)BB * NN * 3 * CC];        // (B,N,3C)
__device__ float g_traj [(size_t)BB * SS * FF * CC];       // (B,S,F,C)
__device__ float g_xdiag[(size_t)BB * SS * CC];            // (B,S,C)
__device__ float g_q2   [(size_t)BB * SS * CC];            // (B,S,C)
__device__ float g_k2   [(size_t)BB * SS * FF * CC];       // (B,S,F,C)
__device__ float g_cat  [(size_t)BB * NN * CC];            // (B,N,C): row0=cls_out, rows1..=temporal out

// ---------------- generic tiled SGEMM: C = A(MxK) @ B(KxN) [+bias] --------
__global__ void __launch_bounds__(256) sgemm_kernel(
    const float* __restrict__ A, const float* __restrict__ B,
    const float* __restrict__ bias, float* __restrict__ C,
    int M, int N, int K, int lda, int ldb, int ldc)
{
    __shared__ float As[16][65];
    __shared__ float Bs[16][64];
    const int tid = threadIdx.x;
    const int tx = tid & 15, ty = tid >> 4;
    const int m0 = blockIdx.y * 64, n0 = blockIdx.x * 64;
    const int arow = tid >> 2, acol = (tid & 3) << 2;   // A tile: 64 rows x 16 k
    const int brow = tid >> 4, bcol = (tid & 15) << 2;  // B tile: 16 k x 64 cols
    const bool arow_ok = (m0 + arow) < M;
    const float* Ap = A + (size_t)(m0 + arow) * lda + acol;
    const float* Bp = B + (size_t)brow * ldb + n0 + bcol;

    float acc[4][4] = {};
    for (int k0 = 0; k0 < K; k0 += 16) {
        float4 av = make_float4(0.f, 0.f, 0.f, 0.f);
        if (arow_ok) av = *(const float4*)(Ap + k0);
        float4 bv = *(const float4*)(Bp + (size_t)k0 * ldb);
        As[acol + 0][arow] = av.x;
        As[acol + 1][arow] = av.y;
        As[acol + 2][arow] = av.z;
        As[acol + 3][arow] = av.w;
        *(float4*)&Bs[brow][bcol] = bv;
        __syncthreads();
#pragma unroll
        for (int kk = 0; kk < 16; kk++) {
            float a0 = As[kk][ty * 4 + 0];
            float a1 = As[kk][ty * 4 + 1];
            float a2 = As[kk][ty * 4 + 2];
            float a3 = As[kk][ty * 4 + 3];
            float4 b4 = *(const float4*)&Bs[kk][tx * 4];
            acc[0][0] += a0 * b4.x; acc[0][1] += a0 * b4.y; acc[0][2] += a0 * b4.z; acc[0][3] += a0 * b4.w;
            acc[1][0] += a1 * b4.x; acc[1][1] += a1 * b4.y; acc[1][2] += a1 * b4.z; acc[1][3] += a1 * b4.w;
            acc[2][0] += a2 * b4.x; acc[2][1] += a2 * b4.y; acc[2][2] += a2 * b4.z; acc[2][3] += a2 * b4.w;
            acc[3][0] += a3 * b4.x; acc[3][1] += a3 * b4.y; acc[3][2] += a3 * b4.z; acc[3][3] += a3 * b4.w;
        }
        __syncthreads();
    }
#pragma unroll
    for (int i = 0; i < 4; i++) {
        int row = m0 + ty * 4 + i;
        if (row >= M) continue;
#pragma unroll
        for (int j = 0; j < 4; j++) {
            int col = n0 + tx * 4 + j;
            float v = acc[i][j];
            if (bias) v += bias[col];
            C[(size_t)row * ldc + col] = v;
        }
    }
}

// ---------------- cls-token attention -> g_cat row 0 per batch ------------
__global__ void __launch_bounds__(128) cls_kernel()
{
    __shared__ float sims[NN];
    __shared__ float shq[DD];
    __shared__ float red[128];
    const int bh = blockIdx.x;
    const int b = bh / HH, h = bh % HH;
    const int tid = threadIdx.x;

    if (tid < DD)
        shq[tid] = g_qkv[(size_t)(b * NN) * (3 * CC) + h * DD + tid] * SCALE;
    __syncthreads();

    for (int n = tid; n < NN; n += 128) {
        const float* kr = g_qkv + (size_t)(b * NN + n) * (3 * CC) + CC + h * DD;
        float dot = 0.f;
#pragma unroll
        for (int dd = 0; dd < DD; dd++) dot += shq[dd] * kr[dd];
        sims[n] = dot;
    }
    __syncthreads();

    float m = -1e30f;
    for (int n = tid; n < NN; n += 128) m = fmaxf(m, sims[n]);
    red[tid] = m; __syncthreads();
    for (int st = 64; st; st >>= 1) {
        if (tid < st) red[tid] = fmaxf(red[tid], red[tid + st]);
        __syncthreads();
    }
    m = red[0];
    __syncthreads();

    float sm = 0.f;
    for (int n = tid; n < NN; n += 128) {
        float e = __expf(sims[n] - m);
        sims[n] = e;
        sm += e;
    }
    red[tid] = sm; __syncthreads();
    for (int st = 64; st; st >>= 1) {
        if (tid < st) red[tid] += red[tid + st];
        __syncthreads();
    }
    const float inv = 1.f / red[0];
    __syncthreads();

    if (tid < DD) {
        float acc = 0.f;
        for (int n = 0; n < NN; n++)
            acc += sims[n] * g_qkv[(size_t)(b * NN + n) * (3 * CC) + 2 * CC + h * DD + tid];
        g_cat[(size_t)(b * NN) * CC + h * DD + tid] = acc * inv;
    }
}

// ---------------- fused space attention -> traj ---------------------------
// grid: (S/TQ, B*H), block: 256 (8 warps, warp = frame)
#define TQ 8
__global__ void __launch_bounds__(256) space_attn_kernel()
{
    extern __shared__ float sh[];
    float* sh_q  = sh;            // TQ*64
    float* sh_sc = sh + TQ * DD;  // TQ*1568

    const int bh = blockIdx.y;
    const int b = bh / HH, h = bh % HH;
    const int s0 = blockIdx.x * TQ;
    const int tid = threadIdx.x;

    for (int i = tid; i < TQ * DD; i += 256) {
        int qi = i >> 6, dd = i & 63;
        sh_q[i] = g_qkv[(size_t)(b * NN + 1 + s0 + qi) * (3 * CC) + h * DD + dd];
    }
    __syncthreads();

    // scores: each thread handles strided keys, all TQ queries
    for (int j = tid; j < SS; j += 256) {
        const float4* krow = (const float4*)(g_qkv + (size_t)(b * NN + 1 + j) * (3 * CC) + CC + h * DD);
        float4 kr[16];
#pragma unroll
        for (int t = 0; t < 16; t++) kr[t] = krow[t];
#pragma unroll
        for (int qi = 0; qi < TQ; qi++) {
            const float* qv = sh_q + qi * DD;
            float dot = 0.f;
#pragma unroll
            for (int t = 0; t < 16; t++) {
                dot += kr[t].x * qv[4 * t + 0] + kr[t].y * qv[4 * t + 1]
                     + kr[t].z * qv[4 * t + 2] + kr[t].w * qv[4 * t + 3];
            }
            sh_sc[qi * SS + j] = dot * SCALE;
        }
    }
    __syncthreads();

    // per-frame softmax + weighted-v; warp f owns frame f
    const int f = tid >> 5, lane = tid & 31;
    float inv[TQ];
#pragma unroll
    for (int qi = 0; qi < TQ; qi++) {
        float* sc = sh_sc + qi * SS + f * PP;
        float m = -1e30f;
        for (int p = lane; p < PP; p += 32) m = fmaxf(m, sc[p]);
#pragma unroll
        for (int o = 16; o; o >>= 1) m = fmaxf(m, __shfl_xor_sync(~0u, m, o));
        float sm = 0.f;
        for (int p = lane; p < PP; p += 32) {
            float e = __expf(sc[p] - m);
            sc[p] = e;
            sm += e;
        }
#pragma unroll
        for (int o = 16; o; o >>= 1) sm += __shfl_xor_sync(~0u, sm, o);
        inv[qi] = 1.f / sm;
    }

    float acc[TQ][2] = {};
    const int j1 = lane, j2 = lane + 32;
    for (int p = 0; p < PP; p++) {
        const float* vrow = g_qkv + (size_t)(b * NN + 1 + f * PP + p) * (3 * CC) + 2 * CC + h * DD;
        float v1 = vrow[j1], v2 = vrow[j2];
#pragma unroll
        for (int qi = 0; qi < TQ; qi++) {
            float a = sh_sc[qi * SS + f * PP + p];
            acc[qi][0] += a * v1;
            acc[qi][1] += a * v2;
        }
    }
#pragma unroll
    for (int qi = 0; qi < TQ; qi++) {
        size_t o = (size_t)((b * SS + s0 + qi) * FF + f) * CC + h * DD;
        g_traj[o + j1] = acc[qi][0] * inv[qi];
        g_traj[o + j2] = acc[qi][1] * inv[qi];
    }
}

// ---------------- x_diag gather -------------------------------------------
__global__ void xdiag_kernel()
{
    size_t idx = (size_t)blockIdx.x * 256 + threadIdx.x;
    if (idx >= (size_t)BB * SS * CC) return;
    int c = (int)(idx % CC);
    int m = (int)(idx / CC);          // b*S + s
    int s = m % SS;
    g_xdiag[idx] = g_traj[(size_t)(m * FF + s / PP) * CC + c];
}

// ---------------- temporal attention + attn output ------------------------
// grid: B*S blocks, 384 threads (12 warps, warp = head)
__global__ void __launch_bounds__(384) temporal_kernel(float* __restrict__ attn_out)
{
    const int m = blockIdx.x;               // b*S + s
    const int b = m / SS, s = m % SS;
    const int h = threadIdx.x >> 5;
    const int lane = threadIdx.x & 31;

    const size_t q2off = (size_t)m * CC + h * DD;
    const float qa = g_q2[q2off + lane];
    const float qb = g_q2[q2off + lane + 32];

    float logit[FF];
#pragma unroll
    for (int f = 0; f < FF; f++) {
        size_t k2off = (size_t)(m * FF + f) * CC + h * DD;
        float pr = qa * g_k2[k2off + lane] + qb * g_k2[k2off + lane + 32];
#pragma unroll
        for (int o = 16; o; o >>= 1) pr += __shfl_xor_sync(~0u, pr, o);
        logit[f] = pr * SCALE;
    }
    float mx = logit[0];
#pragma unroll
    for (int f = 1; f < FF; f++) mx = fmaxf(mx, logit[f]);
    float a[FF], sm = 0.f;
#pragma unroll
    for (int f = 0; f < FF; f++) { a[f] = __expf(logit[f] - mx); sm += a[f]; }
    const float inv = 1.f / sm;

    // attn output: (B, H, S, F)
    const size_t aoff = ((size_t)(b * HH + h) * SS + s) * FF;
#pragma unroll
    for (int f = 0; f < FF; f++)
        if (lane == f) attn_out[aoff + f] = a[f] * inv;

    float acc1 = 0.f, acc2 = 0.f;
#pragma unroll
    for (int f = 0; f < FF; f++) {
        size_t toff = (size_t)(m * FF + f) * CC + h * DD;
        float w = a[f] * inv;
        acc1 += w * g_traj[toff + lane];
        acc2 += w * g_traj[toff + lane + 32];
    }
    const size_t co = (size_t)(b * NN + 1 + s) * CC + h * DD;
    g_cat[co + lane] = acc1;
    g_cat[co + lane + 32] = acc2;
}

// ---------------- launch ---------------------------------------------------
extern "C" void kernel_launch(void* const* d_in, const int* in_sizes, int n_in,
                              void* d_out, int out_size)
{
    const float* x      = (const float*)d_in[0];
    const float* W_qkv  = (const float*)d_in[1];
    const float* W_pq   = (const float*)d_in[2];
    const float* W_pkv  = (const float*)d_in[3];
    const float* W_proj = (const float*)d_in[4];
    const float* b_proj = (const float*)d_in[5];
    float* out  = (float*)d_out;                       // (B,N,C)
    float* attn = out + (size_t)BB * NN * CC;          // (B,H,S,F)

    float *p_qkv, *p_traj, *p_xdiag, *p_q2, *p_k2, *p_cat;
    cudaGetSymbolAddress((void**)&p_qkv,   g_qkv);
    cudaGetSymbolAddress((void**)&p_traj,  g_traj);
    cudaGetSymbolAddress((void**)&p_xdiag, g_xdiag);
    cudaGetSymbolAddress((void**)&p_q2,    g_q2);
    cudaGetSymbolAddress((void**)&p_k2,    g_k2);
    cudaGetSymbolAddress((void**)&p_cat,   g_cat);

    const int space_smem = (TQ * DD + TQ * SS) * 4;    // 52224 B
    cudaFuncSetAttribute(space_attn_kernel,
                         cudaFuncAttributeMaxDynamicSharedMemorySize, space_smem);

    // 1. qkv = x @ W_qkv    (M=3138, N=2304, K=768)
    {
        dim3 grid((3 * CC + 63) / 64, (BB * NN + 63) / 64);
        sgemm_kernel<<<grid, 256>>>(x, W_qkv, nullptr, p_qkv,
                                    BB * NN, 3 * CC, CC, CC, 3 * CC, 3 * CC);
    }
    // 2. cls attention -> g_cat rows b*N
    cls_kernel<<<BH, 128>>>();
    // 3. space attention -> g_traj
    {
        dim3 grid(SS / TQ, BH);
        space_attn_kernel<<<grid, 256, space_smem>>>();
    }
    // 4. x_diag gather
    {
        size_t n = (size_t)BB * SS * CC;
        xdiag_kernel<<<(unsigned)((n + 255) / 256), 256>>>();
    }
    // 5. q2 = x_diag @ W_pq  (M=3136, N=768, K=768)
    {
        dim3 grid(CC / 64, (BB * SS + 63) / 64);
        sgemm_kernel<<<grid, 256>>>(p_xdiag, W_pq, nullptr, p_q2,
                                    BB * SS, CC, CC, CC, CC, CC);
    }
    // 6. k2 = traj @ W_pkv[:, :768]  (M=25088, N=768, K=768, ldb=1536)
    {
        dim3 grid(CC / 64, (BB * SS * FF + 63) / 64);
        sgemm_kernel<<<grid, 256>>>(p_traj, W_pkv, nullptr, p_k2,
                                    BB * SS * FF, CC, CC, CC, 2 * CC, CC);
    }
    // 7. temporal attention -> g_cat rows, attn -> d_out tail
    temporal_kernel<<<BB * SS, 384>>>(attn);
    // 8. out = g_cat @ W_proj + b_proj  -> d_out head (M=3138, N=768, K=768)
    {
        dim3 grid(CC / 64, (BB * NN + 63) / 64);
        sgemm_kernel<<<grid, 256>>>(p_cat, W_proj, b_proj, out,
                                    BB * NN, CC, CC, CC, CC, CC);
    }
}

// round 7
// speedup vs baseline: 1.2582x; 1.2582x over previous
#include <cuda_runtime.h>
#include <cuda_bf16.h>
#include <cstdint>
#include <cstddef>

// Problem constants
#define BB 2
#define NN 1569
#define CC 768
#define HH 12
#define DD 64
#define FF 8
#define PP 196
#define SS 1568        // F*P
#define BH 24          // B*H
#define SCALE 0.125f   // d^-0.5

// ---------------- scratch (device globals; no allocation) ----------------
__device__ float g_qkv  [(size_t)BB * NN * 3 * CC];        // (B,N,3C)
__device__ float g_traj [(size_t)BB * SS * FF * CC];       // (B,S,F,C)
__device__ float g_xdiag[(size_t)BB * SS * CC];            // (B,S,C)
__device__ float g_q2   [(size_t)BB * SS * CC];            // (B,S,C)
__device__ float g_k2   [(size_t)BB * SS * FF * CC];       // (B,S,F,C)
__device__ float g_cat  [(size_t)BB * NN * CC];            // (B,N,C)

// bf16 split weight pool: [hi | lo], each 4608*768 elems
// layout rows (transposed, [N,K] K-major): qkv(2304) | pq(768) | pkv_k(768) | proj(768)
#define WPOOL_ROWS 4608
__device__ __nv_bfloat16 g_wb[2][(size_t)WPOOL_ROWS * CC];
#define WOFF_QKV  0
#define WOFF_PQ   (2304 * CC)
#define WOFF_PKVK (3072 * CC)
#define WOFF_PROJ (3840 * CC)

// ====================== warp-MMA helpers (compute_103-safe) ================
__device__ __forceinline__ uint32_t smem_to_u32(const void* p) {
    uint32_t a;
    asm("{ .reg .u64 t; cvta.to.shared.u64 t, %1; cvt.u32.u64 %0, t; }" : "=r"(a) : "l"(p));
    return a;
}
__device__ __forceinline__ void ldsm_x4(uint32_t& d0, uint32_t& d1, uint32_t& d2, uint32_t& d3,
                                        uint32_t a) {
    asm volatile("ldmatrix.sync.aligned.m8n8.x4.shared.b16 {%0,%1,%2,%3}, [%4];"
                 : "=r"(d0), "=r"(d1), "=r"(d2), "=r"(d3) : "r"(a));
}
__device__ __forceinline__ void ldsm_x2(uint32_t& d0, uint32_t& d1, uint32_t a) {
    asm volatile("ldmatrix.sync.aligned.m8n8.x2.shared.b16 {%0,%1}, [%2];"
                 : "=r"(d0), "=r"(d1) : "r"(a));
}
__device__ __forceinline__ void mma_bf16(float* c, const uint32_t* a, const uint32_t* b) {
    asm volatile(
        "mma.sync.aligned.m16n8k16.row.col.f32.bf16.bf16.f32 "
        "{%0,%1,%2,%3}, {%4,%5,%6,%7}, {%8,%9}, {%0,%1,%2,%3};"
        : "+f"(c[0]), "+f"(c[1]), "+f"(c[2]), "+f"(c[3])
        : "r"(a[0]), "r"(a[1]), "r"(a[2]), "r"(a[3]), "r"(b[0]), "r"(b[1]));
}

// ============ transpose + bf16-split of a weight block =====================
// in: fp32 [K, >=c0+Nt] row-major stride ldb. out (pool rows base woff): [Nt, K] bf16 hi/lo.
__global__ void __launch_bounds__(256) transpose_split_kernel(
    const float* __restrict__ in, int ldb, int c0, size_t woff, int Nt)
{
    __shared__ float tile[32][33];
    const int nb = blockIdx.x * 32, kb = blockIdx.y * 32;
    const int tx = threadIdx.x & 31, ty = threadIdx.x >> 5;   // 32 x 8
#pragma unroll
    for (int i = 0; i < 32; i += 8)
        tile[ty + i][tx] = in[(size_t)(kb + ty + i) * ldb + c0 + nb + tx];
    __syncthreads();
#pragma unroll
    for (int i = 0; i < 32; i += 8) {
        float v = tile[tx][ty + i];
        __nv_bfloat16 hi = __float2bfloat16(v);
        __nv_bfloat16 lo = __float2bfloat16(v - __bfloat162float(hi));
        size_t o = woff + (size_t)(nb + ty + i) * CC + kb + tx;
        g_wb[0][o] = hi;
        g_wb[1][o] = lo;
    }
}

// ================== bf16x3 HMMA GEMM =======================================
// C[M,N] = A[M,K]fp32 @ Bt[N,K]^T (bf16 split, pool offset woff) [+bias]
// block tile 128x128, K-chunk 64, 256 threads = 8 warps (2 M x 4 N),
// warp tile 64x32 via m16n8k16. 3 passes: Ahi*Bhi + Ahi*Blo + Alo*Bhi.
// smem layout per pool: row r (128 rows) x 64 bf16 (128 B), 16B-chunk swizzle
//   byte_off(r, kch) = r*128 + ((kch ^ (r&7)) << 4)
#define SM_AHI 0
#define SM_ALO 16384
#define SM_BHI 32768
#define SM_BLO 49152
#define SM_TOT 65536

__global__ void __launch_bounds__(256) tc_gemm_kernel(
    const float* __restrict__ A, size_t woff, const float* __restrict__ bias,
    float* __restrict__ C, int M, int N, int K)
{
    extern __shared__ char smem[];
    const uint32_t smu = smem_to_u32(smem);
    const int tid = threadIdx.x, wid = tid >> 5, lane = tid & 31;
    const int wm = wid >> 2, wn = wid & 3;           // 2 x 4 warps
    const int m0 = blockIdx.x * 128, n0 = blockIdx.y * 128;
    const __nv_bfloat16* Bt_hi = &g_wb[0][woff];
    const __nv_bfloat16* Bt_lo = &g_wb[1][woff];

    float acc[4][4][4];
#pragma unroll
    for (int i = 0; i < 4; i++)
#pragma unroll
        for (int j = 0; j < 4; j++)
#pragma unroll
            for (int t = 0; t < 4; t++) acc[i][j][t] = 0.f;

    const int nchunks = K >> 6;
    for (int kc = 0; kc < nchunks; kc++) {
        const int k0 = kc << 6;
        // ---- A fp32 -> split bf16 hi/lo into smem ----
#pragma unroll
        for (int it = 0; it < 8; it++) {
            int idx = it * 256 + tid;           // 2048 float4 slots
            int r = idx >> 4, cg = idx & 15;    // row, float4-group (4 floats)
            float4 v = make_float4(0.f, 0.f, 0.f, 0.f);
            if (m0 + r < M)
                v = *(const float4*)(A + (size_t)(m0 + r) * K + k0 + cg * 4);
            __nv_bfloat162 h01 = __floats2bfloat162_rn(v.x, v.y);
            __nv_bfloat162 h23 = __floats2bfloat162_rn(v.z, v.w);
            float r0 = v.x - __bfloat162float(h01.x);
            float r1 = v.y - __bfloat162float(h01.y);
            float r2 = v.z - __bfloat162float(h23.x);
            float r3 = v.w - __bfloat162float(h23.y);
            __nv_bfloat162 l01 = __floats2bfloat162_rn(r0, r1);
            __nv_bfloat162 l23 = __floats2bfloat162_rn(r2, r3);
            int ch = cg >> 1;
            uint32_t off = (uint32_t)(r * 128 + ((ch ^ (r & 7)) << 4) + (cg & 1) * 8);
            *(uint2*)(smem + SM_AHI + off) = make_uint2(*(uint32_t*)&h01, *(uint32_t*)&h23);
            *(uint2*)(smem + SM_ALO + off) = make_uint2(*(uint32_t*)&l01, *(uint32_t*)&l23);
        }
        // ---- B pre-split bf16 -> smem ----
#pragma unroll
        for (int it = 0; it < 4; it++) {
            int idx = it * 256 + tid;           // 1024 16B chunks
            int r = idx >> 3, ch = idx & 7;
            uint32_t off = (uint32_t)(r * 128 + ((ch ^ (r & 7)) << 4));
            const size_t go = (size_t)(n0 + r) * K + k0 + ch * 8;
            *(uint4*)(smem + SM_BHI + off) = *(const uint4*)(Bt_hi + go);
            *(uint4*)(smem + SM_BLO + off) = *(const uint4*)(Bt_lo + go);
        }
        __syncthreads();

#pragma unroll
        for (int ks = 0; ks < 4; ks++) {
            uint32_t ahi[4][4], alo[4][4], bhi[4][2], blo[4][2];
#pragma unroll
            for (int i = 0; i < 4; i++) {
                int mi = lane >> 3;                         // matrix idx 0..3
                int row = wm * 64 + i * 16 + ((mi & 1) << 3) + (lane & 7);
                int kch = ks * 2 + (mi >> 1);
                uint32_t off = (uint32_t)(row * 128 + ((kch ^ (row & 7)) << 4));
                ldsm_x4(ahi[i][0], ahi[i][1], ahi[i][2], ahi[i][3], smu + SM_AHI + off);
                ldsm_x4(alo[i][0], alo[i][1], alo[i][2], alo[i][3], smu + SM_ALO + off);
            }
#pragma unroll
            for (int j = 0; j < 4; j++) {
                int l = lane & 15;
                int mi = l >> 3;
                int n = wn * 32 + j * 8 + (l & 7);
                int kch = ks * 2 + mi;
                uint32_t off = (uint32_t)(n * 128 + ((kch ^ (n & 7)) << 4));
                ldsm_x2(bhi[j][0], bhi[j][1], smu + SM_BHI + off);
                ldsm_x2(blo[j][0], blo[j][1], smu + SM_BLO + off);
            }
#pragma unroll
            for (int i = 0; i < 4; i++)
#pragma unroll
                for (int j = 0; j < 4; j++) {
                    mma_bf16(acc[i][j], ahi[i], bhi[j]);
                    mma_bf16(acc[i][j], ahi[i], blo[j]);
                    mma_bf16(acc[i][j], alo[i], bhi[j]);
                }
        }
        __syncthreads();
    }

    // ---- epilogue ----
#pragma unroll
    for (int i = 0; i < 4; i++) {
        int rbase = m0 + wm * 64 + i * 16 + (lane >> 2);
#pragma unroll
        for (int j = 0; j < 4; j++) {
            int col = n0 + wn * 32 + j * 8 + (lane & 3) * 2;
            float b0 = bias ? bias[col] : 0.f;
            float b1 = bias ? bias[col + 1] : 0.f;
            if (rbase < M) {
                float2 v = make_float2(acc[i][j][0] + b0, acc[i][j][1] + b1);
                *(float2*)(C + (size_t)rbase * N + col) = v;
            }
            if (rbase + 8 < M) {
                float2 v = make_float2(acc[i][j][2] + b0, acc[i][j][3] + b1);
                *(float2*)(C + (size_t)(rbase + 8) * N + col) = v;
            }
        }
    }
}

// ---------------- cls-token attention -> g_cat row 0 per batch ------------
__global__ void __launch_bounds__(128) cls_kernel()
{
    __shared__ float sims[NN];
    __shared__ float shq[DD];
    __shared__ float red[128];
    const int bh = blockIdx.x;
    const int b = bh / HH, h = bh % HH;
    const int tid = threadIdx.x;

    if (tid < DD)
        shq[tid] = g_qkv[(size_t)(b * NN) * (3 * CC) + h * DD + tid] * SCALE;
    __syncthreads();

    for (int n = tid; n < NN; n += 128) {
        const float* kr = g_qkv + (size_t)(b * NN + n) * (3 * CC) + CC + h * DD;
        float dot = 0.f;
#pragma unroll
        for (int dd = 0; dd < DD; dd++) dot += shq[dd] * kr[dd];
        sims[n] = dot;
    }
    __syncthreads();

    float m = -1e30f;
    for (int n = tid; n < NN; n += 128) m = fmaxf(m, sims[n]);
    red[tid] = m; __syncthreads();
    for (int st = 64; st; st >>= 1) {
        if (tid < st) red[tid] = fmaxf(red[tid], red[tid + st]);
        __syncthreads();
    }
    m = red[0];
    __syncthreads();

    float sm = 0.f;
    for (int n = tid; n < NN; n += 128) {
        float e = __expf(sims[n] - m);
        sims[n] = e;
        sm += e;
    }
    red[tid] = sm; __syncthreads();
    for (int st = 64; st; st >>= 1) {
        if (tid < st) red[tid] += red[tid + st];
        __syncthreads();
    }
    const float inv = 1.f / red[0];
    __syncthreads();

    if (tid < DD) {
        float acc = 0.f;
        for (int n = 0; n < NN; n++)
            acc += sims[n] * g_qkv[(size_t)(b * NN + n) * (3 * CC) + 2 * CC + h * DD + tid];
        g_cat[(size_t)(b * NN) * CC + h * DD + tid] = acc * inv;
    }
}

// ---------------- fused space attention -> traj ---------------------------
#define TQ 8
__global__ void __launch_bounds__(256) space_attn_kernel()
{
    extern __shared__ float sh[];
    float* sh_q  = sh;            // TQ*64
    float* sh_sc = sh + TQ * DD;  // TQ*1568

    const int bh = blockIdx.y;
    const int b = bh / HH, h = bh % HH;
    const int s0 = blockIdx.x * TQ;
    const int tid = threadIdx.x;

    for (int i = tid; i < TQ * DD; i += 256) {
        int qi = i >> 6, dd = i & 63;
        sh_q[i] = g_qkv[(size_t)(b * NN + 1 + s0 + qi) * (3 * CC) + h * DD + dd];
    }
    __syncthreads();

    for (int j = tid; j < SS; j += 256) {
        const float4* krow = (const float4*)(g_qkv + (size_t)(b * NN + 1 + j) * (3 * CC) + CC + h * DD);
        float4 kr[16];
#pragma unroll
        for (int t = 0; t < 16; t++) kr[t] = krow[t];
#pragma unroll
        for (int qi = 0; qi < TQ; qi++) {
            const float* qv = sh_q + qi * DD;
            float dot = 0.f;
#pragma unroll
            for (int t = 0; t < 16; t++) {
                dot += kr[t].x * qv[4 * t + 0] + kr[t].y * qv[4 * t + 1]
                     + kr[t].z * qv[4 * t + 2] + kr[t].w * qv[4 * t + 3];
            }
            sh_sc[qi * SS + j] = dot * SCALE;
        }
    }
    __syncthreads();

    const int f = tid >> 5, lane = tid & 31;
    float inv[TQ];
#pragma unroll
    for (int qi = 0; qi < TQ; qi++) {
        float* sc = sh_sc + qi * SS + f * PP;
        float m = -1e30f;
        for (int p = lane; p < PP; p += 32) m = fmaxf(m, sc[p]);
#pragma unroll
        for (int o = 16; o; o >>= 1) m = fmaxf(m, __shfl_xor_sync(~0u, m, o));
        float sm = 0.f;
        for (int p = lane; p < PP; p += 32) {
            float e = __expf(sc[p] - m);
            sc[p] = e;
            sm += e;
        }
#pragma unroll
        for (int o = 16; o; o >>= 1) sm += __shfl_xor_sync(~0u, sm, o);
        inv[qi] = 1.f / sm;
    }

    float acc[TQ][2] = {};
    const int j1 = lane, j2 = lane + 32;
    for (int p = 0; p < PP; p++) {
        const float* vrow = g_qkv + (size_t)(b * NN + 1 + f * PP + p) * (3 * CC) + 2 * CC + h * DD;
        float v1 = vrow[j1], v2 = vrow[j2];
#pragma unroll
        for (int qi = 0; qi < TQ; qi++) {
            float a = sh_sc[qi * SS + f * PP + p];
            acc[qi][0] += a * v1;
            acc[qi][1] += a * v2;
        }
    }
#pragma unroll
    for (int qi = 0; qi < TQ; qi++) {
        size_t o = (size_t)((b * SS + s0 + qi) * FF + f) * CC + h * DD;
        g_traj[o + j1] = acc[qi][0] * inv[qi];
        g_traj[o + j2] = acc[qi][1] * inv[qi];
    }
}

// ---------------- x_diag gather -------------------------------------------
__global__ void xdiag_kernel()
{
    size_t idx = (size_t)blockIdx.x * 256 + threadIdx.x;
    if (idx >= (size_t)BB * SS * CC) return;
    int c = (int)(idx % CC);
    int m = (int)(idx / CC);
    int s = m % SS;
    g_xdiag[idx] = g_traj[(size_t)(m * FF + s / PP) * CC + c];
}

// ---------------- temporal attention + attn output ------------------------
__global__ void __launch_bounds__(384) temporal_kernel(float* __restrict__ attn_out)
{
    const int m = blockIdx.x;
    const int b = m / SS, s = m % SS;
    const int h = threadIdx.x >> 5;
    const int lane = threadIdx.x & 31;

    const size_t q2off = (size_t)m * CC + h * DD;
    const float qa = g_q2[q2off + lane];
    const float qb = g_q2[q2off + lane + 32];

    float logit[FF];
#pragma unroll
    for (int f = 0; f < FF; f++) {
        size_t k2off = (size_t)(m * FF + f) * CC + h * DD;
        float pr = qa * g_k2[k2off + lane] + qb * g_k2[k2off + lane + 32];
#pragma unroll
        for (int o = 16; o; o >>= 1) pr += __shfl_xor_sync(~0u, pr, o);
        logit[f] = pr * SCALE;
    }
    float mx = logit[0];
#pragma unroll
    for (int f = 1; f < FF; f++) mx = fmaxf(mx, logit[f]);
    float a[FF], sm = 0.f;
#pragma unroll
    for (int f = 0; f < FF; f++) { a[f] = __expf(logit[f] - mx); sm += a[f]; }
    const float inv = 1.f / sm;

    const size_t aoff = ((size_t)(b * HH + h) * SS + s) * FF;
#pragma unroll
    for (int f = 0; f < FF; f++)
        if (lane == f) attn_out[aoff + f] = a[f] * inv;

    float acc1 = 0.f, acc2 = 0.f;
#pragma unroll
    for (int f = 0; f < FF; f++) {
        size_t toff = (size_t)(m * FF + f) * CC + h * DD;
        float w = a[f] * inv;
        acc1 += w * g_traj[toff + lane];
        acc2 += w * g_traj[toff + lane + 32];
    }
    const size_t co = (size_t)(b * NN + 1 + s) * CC + h * DD;
    g_cat[co + lane] = acc1;
    g_cat[co + lane + 32] = acc2;
}

// ---------------- launch ---------------------------------------------------
extern "C" void kernel_launch(void* const* d_in, const int* in_sizes, int n_in,
                              void* d_out, int out_size)
{
    const float* x      = (const float*)d_in[0];
    const float* W_qkv  = (const float*)d_in[1];
    const float* W_pq   = (const float*)d_in[2];
    const float* W_pkv  = (const float*)d_in[3];
    const float* W_proj = (const float*)d_in[4];
    const float* b_proj = (const float*)d_in[5];
    float* out  = (float*)d_out;                       // (B,N,C)
    float* attn = out + (size_t)BB * NN * CC;          // (B,H,S,F)

    float *p_qkv, *p_traj, *p_xdiag, *p_q2, *p_k2, *p_cat;
    cudaGetSymbolAddress((void**)&p_qkv,   g_qkv);
    cudaGetSymbolAddress((void**)&p_traj,  g_traj);
    cudaGetSymbolAddress((void**)&p_xdiag, g_xdiag);
    cudaGetSymbolAddress((void**)&p_q2,    g_q2);
    cudaGetSymbolAddress((void**)&p_k2,    g_k2);
    cudaGetSymbolAddress((void**)&p_cat,   g_cat);

    const int space_smem = (TQ * DD + TQ * SS) * 4;    // 52224 B
    cudaFuncSetAttribute(space_attn_kernel,
                         cudaFuncAttributeMaxDynamicSharedMemorySize, space_smem);
    cudaFuncSetAttribute(tc_gemm_kernel,
                         cudaFuncAttributeMaxDynamicSharedMemorySize, SM_TOT);

    // 0. weight transpose + bf16 split
    transpose_split_kernel<<<dim3(2304 / 32, CC / 32), 256>>>(W_qkv, 3 * CC, 0, WOFF_QKV, 2304);
    transpose_split_kernel<<<dim3(CC / 32, CC / 32), 256>>>(W_pq, CC, 0, WOFF_PQ, CC);
    transpose_split_kernel<<<dim3(CC / 32, CC / 32), 256>>>(W_pkv, 2 * CC, 0, WOFF_PKVK, CC);
    transpose_split_kernel<<<dim3(CC / 32, CC / 32), 256>>>(W_proj, CC, 0, WOFF_PROJ, CC);

    // 1. qkv = x @ W_qkv    (M=3138, N=2304, K=768)
    tc_gemm_kernel<<<dim3((BB * NN + 127) / 128, 2304 / 128), 256, SM_TOT>>>(
        x, WOFF_QKV, nullptr, p_qkv, BB * NN, 3 * CC, CC);
    // 2. cls attention
    cls_kernel<<<BH, 128>>>();
    // 3. space attention -> g_traj
    space_attn_kernel<<<dim3(SS / TQ, BH), 256, space_smem>>>();
    // 4. x_diag gather
    {
        size_t n = (size_t)BB * SS * CC;
        xdiag_kernel<<<(unsigned)((n + 255) / 256), 256>>>();
    }
    // 5. q2 = x_diag @ W_pq  (M=3136, N=768, K=768)
    tc_gemm_kernel<<<dim3((BB * SS + 127) / 128, CC / 128), 256, SM_TOT>>>(
        p_xdiag, WOFF_PQ, nullptr, p_q2, BB * SS, CC, CC);
    // 6. k2 = traj @ W_pkv[:, :768]  (M=25088, N=768, K=768)
    tc_gemm_kernel<<<dim3((BB * SS * FF + 127) / 128, CC / 128), 256, SM_TOT>>>(
        p_traj, WOFF_PKVK, nullptr, p_k2, BB * SS * FF, CC, CC);
    // 7. temporal attention
    temporal_kernel<<<BB * SS, 384>>>(attn);
    // 8. out = g_cat @ W_proj + b_proj  (M=3138, N=768, K=768)
    tc_gemm_kernel<<<dim3((BB * NN + 127) / 128, CC / 128), 256, SM_TOT>>>(
        p_cat, WOFF_PROJ, b_proj, out, BB * NN, CC, CC);
}

// round 11
// speedup vs baseline: 4.3905x; 3.4895x over previous
#include <cuda_runtime.h>
#include <cuda_bf16.h>
#include <cstdint>
#include <cstddef>

// Problem constants
#define BB 2
#define NN 1569
#define CC 768
#define HH 12
#define DD 64
#define FF 8
#define PP 196
#define SS 1568        // F*P
#define BH 24          // B*H
#define SCALE 0.125f   // d^-0.5

// ---------------- scratch (device globals; no allocation) ----------------
__device__ float g_qkv  [(size_t)BB * NN * 3 * CC];        // (B,N,3C)
__device__ float g_traj [(size_t)BB * SS * FF * CC];       // (B,S,F,C)
__device__ float g_xdiag[(size_t)BB * SS * CC];            // (B,S,C)
__device__ float g_q2   [(size_t)BB * SS * CC];            // (B,S,C)
__device__ float g_k2   [(size_t)BB * SS * FF * CC];       // (B,S,F,C)
__device__ float g_cat  [(size_t)BB * NN * CC];            // (B,N,C)

// bf16 split weight pool: [hi | lo], each 4608*768 elems
#define WPOOL_ROWS 4608
__device__ __nv_bfloat16 g_wb[2][(size_t)WPOOL_ROWS * CC];
#define WOFF_QKV  0
#define WOFF_PQ   (2304 * CC)
#define WOFF_PKVK (3072 * CC)
#define WOFF_PROJ (3840 * CC)

// ====================== warp-MMA helpers (compute_103-safe) ================
__device__ __forceinline__ uint32_t smem_to_u32(const void* p) {
    uint32_t a;
    asm("{ .reg .u64 t; cvta.to.shared.u64 t, %1; cvt.u32.u64 %0, t; }" : "=r"(a) : "l"(p));
    return a;
}
__device__ __forceinline__ void ldsm_x4(uint32_t& d0, uint32_t& d1, uint32_t& d2, uint32_t& d3,
                                        uint32_t a) {
    asm volatile("ldmatrix.sync.aligned.m8n8.x4.shared.b16 {%0,%1,%2,%3}, [%4];"
                 : "=r"(d0), "=r"(d1), "=r"(d2), "=r"(d3) : "r"(a));
}
__device__ __forceinline__ void ldsm_x2(uint32_t& d0, uint32_t& d1, uint32_t a) {
    asm volatile("ldmatrix.sync.aligned.m8n8.x2.shared.b16 {%0,%1}, [%2];"
                 : "=r"(d0), "=r"(d1) : "r"(a));
}
__device__ __forceinline__ void ldsm_x2_t(uint32_t& d0, uint32_t& d1, uint32_t a) {
    asm volatile("ldmatrix.sync.aligned.m8n8.x2.trans.shared.b16 {%0,%1}, [%2];"
                 : "=r"(d0), "=r"(d1) : "r"(a));
}
__device__ __forceinline__ void mma_bf16(float* c, const uint32_t* a, const uint32_t* b) {
    asm volatile(
        "mma.sync.aligned.m16n8k16.row.col.f32.bf16.bf16.f32 "
        "{%0,%1,%2,%3}, {%4,%5,%6,%7}, {%8,%9}, {%0,%1,%2,%3};"
        : "+f"(c[0]), "+f"(c[1]), "+f"(c[2]), "+f"(c[3])
        : "r"(a[0]), "r"(a[1]), "r"(a[2]), "r"(a[3]), "r"(b[0]), "r"(b[1]));
}
// pack two floats into bf16x2 hi + residual lo
__device__ __forceinline__ void split2(float x, float y, uint32_t& hi, uint32_t& lo) {
    __nv_bfloat162 h = __floats2bfloat162_rn(x, y);
    float rx = x - __bfloat162float(h.x);
    float ry = y - __bfloat162float(h.y);
    __nv_bfloat162 l = __floats2bfloat162_rn(rx, ry);
    hi = *(uint32_t*)&h;
    lo = *(uint32_t*)&l;
}
// fast 2^t on the FMA pipe (t <= ~0, clamped), err ~2e-6 rel
__device__ __forceinline__ float fexp2(float t) {
    t = fmaxf(t, -120.f);
    float tr = t + 12582912.0f;                       // round-to-nearest-int magic
    int ki = __float_as_int(tr) - 0x4B400000;
    float f = t - (tr - 12582912.0f);                 // f in [-0.5, 0.5]
    float p = 1.3333558e-3f;
    p = fmaf(p, f, 9.6181291e-3f);
    p = fmaf(p, f, 5.5504109e-2f);
    p = fmaf(p, f, 2.4022651e-1f);
    p = fmaf(p, f, 6.9314718e-1f);
    p = fmaf(p, f, 1.0f);
    return p * __int_as_float((ki + 127) << 23);
}

// ============ transpose + bf16-split of a weight block =====================
__global__ void __launch_bounds__(256) transpose_split_kernel(
    const float* __restrict__ in, int ldb, int c0, size_t woff, int Nt)
{
    __shared__ float tile[32][33];
    const int nb = blockIdx.x * 32, kb = blockIdx.y * 32;
    const int tx = threadIdx.x & 31, ty = threadIdx.x >> 5;
#pragma unroll
    for (int i = 0; i < 32; i += 8)
        tile[ty + i][tx] = in[(size_t)(kb + ty + i) * ldb + c0 + nb + tx];
    __syncthreads();
#pragma unroll
    for (int i = 0; i < 32; i += 8) {
        float v = tile[tx][ty + i];
        __nv_bfloat16 hi = __float2bfloat16(v);
        __nv_bfloat16 lo = __float2bfloat16(v - __bfloat162float(hi));
        size_t o = woff + (size_t)(nb + ty + i) * CC + kb + tx;
        g_wb[0][o] = hi;
        g_wb[1][o] = lo;
    }
}

// ================== bf16x3 HMMA GEMM =======================================
#define SM_AHI 0
#define SM_ALO 16384
#define SM_BHI 32768
#define SM_BLO 49152
#define SM_TOT 65536

__global__ void __launch_bounds__(256) tc_gemm_kernel(
    const float* __restrict__ A, size_t woff, const float* __restrict__ bias,
    float* __restrict__ C, int M, int N, int K)
{
    extern __shared__ char smem[];
    const uint32_t smu = smem_to_u32(smem);
    const int tid = threadIdx.x, wid = tid >> 5, lane = tid & 31;
    const int wm = wid >> 2, wn = wid & 3;
    const int m0 = blockIdx.x * 128, n0 = blockIdx.y * 128;
    const __nv_bfloat16* Bt_hi = &g_wb[0][woff];
    const __nv_bfloat16* Bt_lo = &g_wb[1][woff];

    float acc[4][4][4];
#pragma unroll
    for (int i = 0; i < 4; i++)
#pragma unroll
        for (int j = 0; j < 4; j++)
#pragma unroll
            for (int t = 0; t < 4; t++) acc[i][j][t] = 0.f;

    const int nchunks = K >> 6;
    for (int kc = 0; kc < nchunks; kc++) {
        const int k0 = kc << 6;
#pragma unroll
        for (int it = 0; it < 8; it++) {
            int idx = it * 256 + tid;
            int r = idx >> 4, cg = idx & 15;
            float4 v = make_float4(0.f, 0.f, 0.f, 0.f);
            if (m0 + r < M)
                v = *(const float4*)(A + (size_t)(m0 + r) * K + k0 + cg * 4);
            uint32_t h01, l01, h23, l23;
            split2(v.x, v.y, h01, l01);
            split2(v.z, v.w, h23, l23);
            int ch = cg >> 1;
            uint32_t off = (uint32_t)(r * 128 + ((ch ^ (r & 7)) << 4) + (cg & 1) * 8);
            *(uint2*)(smem + SM_AHI + off) = make_uint2(h01, h23);
            *(uint2*)(smem + SM_ALO + off) = make_uint2(l01, l23);
        }
#pragma unroll
        for (int it = 0; it < 4; it++) {
            int idx = it * 256 + tid;
            int r = idx >> 3, ch = idx & 7;
            uint32_t off = (uint32_t)(r * 128 + ((ch ^ (r & 7)) << 4));
            const size_t go = (size_t)(n0 + r) * K + k0 + ch * 8;
            *(uint4*)(smem + SM_BHI + off) = *(const uint4*)(Bt_hi + go);
            *(uint4*)(smem + SM_BLO + off) = *(const uint4*)(Bt_lo + go);
        }
        __syncthreads();

#pragma unroll
        for (int ks = 0; ks < 4; ks++) {
            uint32_t ahi[4][4], alo[4][4], bhi[4][2], blo[4][2];
#pragma unroll
            for (int i = 0; i < 4; i++) {
                int mi = lane >> 3;
                int row = wm * 64 + i * 16 + ((mi & 1) << 3) + (lane & 7);
                int kch = ks * 2 + (mi >> 1);
                uint32_t off = (uint32_t)(row * 128 + ((kch ^ (row & 7)) << 4));
                ldsm_x4(ahi[i][0], ahi[i][1], ahi[i][2], ahi[i][3], smu + SM_AHI + off);
                ldsm_x4(alo[i][0], alo[i][1], alo[i][2], alo[i][3], smu + SM_ALO + off);
            }
#pragma unroll
            for (int j = 0; j < 4; j++) {
                int l = lane & 15;
                int n = wn * 32 + j * 8 + (l & 7);
                int kch = ks * 2 + (l >> 3);
                uint32_t off = (uint32_t)(n * 128 + ((kch ^ (n & 7)) << 4));
                ldsm_x2(bhi[j][0], bhi[j][1], smu + SM_BHI + off);
                ldsm_x2(blo[j][0], blo[j][1], smu + SM_BLO + off);
            }
#pragma unroll
            for (int i = 0; i < 4; i++)
#pragma unroll
                for (int j = 0; j < 4; j++) {
                    mma_bf16(acc[i][j], ahi[i], bhi[j]);
                    mma_bf16(acc[i][j], ahi[i], blo[j]);
                    mma_bf16(acc[i][j], alo[i], bhi[j]);
                }
        }
        __syncthreads();
    }

#pragma unroll
    for (int i = 0; i < 4; i++) {
        int rbase = m0 + wm * 64 + i * 16 + (lane >> 2);
#pragma unroll
        for (int j = 0; j < 4; j++) {
            int col = n0 + wn * 32 + j * 8 + (lane & 3) * 2;
            float b0 = bias ? bias[col] : 0.f;
            float b1 = bias ? bias[col + 1] : 0.f;
            if (rbase < M) {
                float2 v = make_float2(acc[i][j][0] + b0, acc[i][j][1] + b1);
                *(float2*)(C + (size_t)rbase * N + col) = v;
            }
            if (rbase + 8 < M) {
                float2 v = make_float2(acc[i][j][2] + b0, acc[i][j][3] + b1);
                *(float2*)(C + (size_t)(rbase + 8) * N + col) = v;
            }
        }
    }
}

// ============ tensor-core flash space attention + fused xdiag ==============
// grid (ceil(S/128), B*H), 256 threads (8 warps, each 16 query rows).
// Per frame: S = Q K_f^T (bf16x3, fp32 acc in regs), softmax (poly exp),
// O = P V_f (P reg-resident bf16 hi/lo, V hi/lo via ldmatrix.trans).
#define QT 128
#define KP 208      // 196 padded to 13*16
#define EC2 0.18033688011112042f   // SCALE * log2(e)
#define SP_QHI 0
#define SP_QLO 16384
#define SP_KHI 32768
#define SP_KLO 59392
#define SP_VHI 86016
#define SP_VLO 112640
#define SP_TOT 139264

__global__ void __launch_bounds__(256) space_attn_tc_kernel()
{
    extern __shared__ char smem[];
    const uint32_t smu = smem_to_u32(smem);
    const int tid = threadIdx.x, wid = tid >> 5, lane = tid & 31;
    const int bh = blockIdx.y;
    const int b = bh / HH, h = bh % HH;
    const int s0 = blockIdx.x * QT;

    // ---- Q tile load + split (128 x 64) ----
#pragma unroll
    for (int it = 0; it < 8; it++) {
        int idx = it * 256 + tid;
        int r = idx >> 4, cg = idx & 15;
        float4 v = make_float4(0.f, 0.f, 0.f, 0.f);
        int tq = s0 + r;
        if (tq < SS)
            v = *(const float4*)(g_qkv + (size_t)(b * NN + 1 + tq) * (3 * CC) + h * DD + cg * 4);
        uint32_t h01, l01, h23, l23;
        split2(v.x, v.y, h01, l01);
        split2(v.z, v.w, h23, l23);
        int ch = cg >> 1;
        uint32_t off = (uint32_t)(r * 128 + ((ch ^ (r & 7)) << 4) + (cg & 1) * 8);
        *(uint2*)(smem + SP_QHI + off) = make_uint2(h01, h23);
        *(uint2*)(smem + SP_QLO + off) = make_uint2(l01, l23);
    }

    for (int f = 0; f < FF; f++) {
        __syncthreads();
        // ---- K_f, V_f load + split (208 x 64, rows >=196 zero) ----
#pragma unroll
        for (int it = 0; it < 13; it++) {
            int idx = it * 256 + tid;
            int r = idx >> 4, cg = idx & 15;
            float4 kv = make_float4(0.f, 0.f, 0.f, 0.f);
            float4 vv = make_float4(0.f, 0.f, 0.f, 0.f);
            if (r < PP) {
                const float* tok = g_qkv + (size_t)(b * NN + 1 + f * PP + r) * (3 * CC) + h * DD;
                kv = *(const float4*)(tok + CC + cg * 4);
                vv = *(const float4*)(tok + 2 * CC + cg * 4);
            }
            int ch = cg >> 1;
            uint32_t off = (uint32_t)(r * 128 + ((ch ^ (r & 7)) << 4) + (cg & 1) * 8);
            uint32_t h01, l01, h23, l23;
            split2(kv.x, kv.y, h01, l01);
            split2(kv.z, kv.w, h23, l23);
            *(uint2*)(smem + SP_KHI + off) = make_uint2(h01, h23);
            *(uint2*)(smem + SP_KLO + off) = make_uint2(l01, l23);
            split2(vv.x, vv.y, h01, l01);
            split2(vv.z, vv.w, h23, l23);
            *(uint2*)(smem + SP_VHI + off) = make_uint2(h01, h23);
            *(uint2*)(smem + SP_VLO + off) = make_uint2(l01, l23);
        }
        __syncthreads();

        // ---- QK^T (bf16x3) -> S[26 tiles][4] fp32 ----
        float S[26][4];
#pragma unroll
        for (int nt = 0; nt < 26; nt++) {
            S[nt][0] = 0.f; S[nt][1] = 0.f; S[nt][2] = 0.f; S[nt][3] = 0.f;
        }
#pragma unroll 1
        for (int pass = 0; pass < 3; pass++) {
            const int pA = (pass == 2) ? SP_QLO : SP_QHI;
            const int pB = (pass == 1) ? SP_KLO : SP_KHI;
#pragma unroll 1
            for (int kc = 0; kc < 4; kc++) {
                uint32_t a[4];
                int mi = lane >> 3;
                int arow = wid * 16 + ((mi & 1) << 3) + (lane & 7);
                int akch = kc * 2 + (mi >> 1);
                ldsm_x4(a[0], a[1], a[2], a[3],
                        smu + pA + (uint32_t)(arow * 128 + ((akch ^ (arow & 7)) << 4)));
                int l = lane & 15;
                int bkch = kc * 2 + (l >> 3);
#pragma unroll
                for (int nt = 0; nt < 26; nt++) {
                    uint32_t bb[2];
                    int brow = nt * 8 + (l & 7);
                    ldsm_x2(bb[0], bb[1],
                            smu + pB + (uint32_t)(brow * 128 + ((bkch ^ (brow & 7)) << 4)));
                    mma_bf16(S[nt], a, bb);
                }
            }
        }

        // ---- softmax over key dim (per row, poly exp on FMA pipe) ----
        const int colbase = 2 * (lane & 3);
        float m0 = -1e30f, m1 = -1e30f;
#pragma unroll
        for (int nt = 0; nt < 26; nt++) {
            if (nt * 8 + colbase < PP) {
                m0 = fmaxf(m0, fmaxf(S[nt][0], S[nt][1]));
                m1 = fmaxf(m1, fmaxf(S[nt][2], S[nt][3]));
            }
        }
        m0 = fmaxf(m0, __shfl_xor_sync(~0u, m0, 1));
        m0 = fmaxf(m0, __shfl_xor_sync(~0u, m0, 2));
        m1 = fmaxf(m1, __shfl_xor_sync(~0u, m1, 1));
        m1 = fmaxf(m1, __shfl_xor_sync(~0u, m1, 2));
        const float mc0 = m0 * EC2, mc1 = m1 * EC2;
        float sum0 = 0.f, sum1 = 0.f;
#pragma unroll
        for (int nt = 0; nt < 26; nt++) {
            if (nt * 8 + colbase < PP) {
                S[nt][0] = fexp2(fmaf(S[nt][0], EC2, -mc0));
                S[nt][1] = fexp2(fmaf(S[nt][1], EC2, -mc0));
                S[nt][2] = fexp2(fmaf(S[nt][2], EC2, -mc1));
                S[nt][3] = fexp2(fmaf(S[nt][3], EC2, -mc1));
                sum0 += S[nt][0] + S[nt][1];
                sum1 += S[nt][2] + S[nt][3];
            } else {
                S[nt][0] = 0.f; S[nt][1] = 0.f; S[nt][2] = 0.f; S[nt][3] = 0.f;
            }
        }
        sum0 += __shfl_xor_sync(~0u, sum0, 1);
        sum0 += __shfl_xor_sync(~0u, sum0, 2);
        sum1 += __shfl_xor_sync(~0u, sum1, 1);
        sum1 += __shfl_xor_sync(~0u, sum1, 2);
        const float inv0 = 1.f / sum0, inv1 = 1.f / sum1;

        // ---- O = P V_f (P reg-resident, bf16x3) ----
        float O[8][4];
#pragma unroll
        for (int nt2 = 0; nt2 < 8; nt2++) {
            O[nt2][0] = 0.f; O[nt2][1] = 0.f; O[nt2][2] = 0.f; O[nt2][3] = 0.f;
        }
#pragma unroll
        for (int kc2 = 0; kc2 < 13; kc2++) {
            uint32_t ah[4], al[4];
            split2(S[2 * kc2][0] * inv0, S[2 * kc2][1] * inv0, ah[0], al[0]);
            split2(S[2 * kc2][2] * inv1, S[2 * kc2][3] * inv1, ah[1], al[1]);
            split2(S[2 * kc2 + 1][0] * inv0, S[2 * kc2 + 1][1] * inv0, ah[2], al[2]);
            split2(S[2 * kc2 + 1][2] * inv1, S[2 * kc2 + 1][3] * inv1, ah[3], al[3]);
            int vrow = kc2 * 16 + (lane & 15);
#pragma unroll
            for (int nt2 = 0; nt2 < 8; nt2++) {
                uint32_t bh2[2], bl2[2];
                uint32_t off = (uint32_t)(vrow * 128 + ((nt2 ^ (vrow & 7)) << 4));
                ldsm_x2_t(bh2[0], bh2[1], smu + SP_VHI + off);
                ldsm_x2_t(bl2[0], bl2[1], smu + SP_VLO + off);
                mma_bf16(O[nt2], ah, bh2);
                mma_bf16(O[nt2], ah, bl2);
                mma_bf16(O[nt2], al, bh2);
            }
        }

        // ---- write O (+ fused xdiag) ----
        const int r0 = s0 + wid * 16 + (lane >> 2);
        const int r1 = r0 + 8;
#pragma unroll
        for (int nt2 = 0; nt2 < 8; nt2++) {
            int col = nt2 * 8 + 2 * (lane & 3);
            if (r0 < SS) {
                size_t o = ((size_t)((b * SS + r0) * FF + f)) * CC + h * DD + col;
                float2 v = make_float2(O[nt2][0], O[nt2][1]);
                *(float2*)(g_traj + o) = v;
                if (r0 / PP == f)
                    *(float2*)(g_xdiag + (size_t)(b * SS + r0) * CC + h * DD + col) = v;
            }
            if (r1 < SS) {
                size_t o = ((size_t)((b * SS + r1) * FF + f)) * CC + h * DD + col;
                float2 v = make_float2(O[nt2][2], O[nt2][3]);
                *(float2*)(g_traj + o) = v;
                if (r1 / PP == f)
                    *(float2*)(g_xdiag + (size_t)(b * SS + r1) * CC + h * DD + col) = v;
            }
        }
    }
}

// ---------------- cls-token attention -> g_cat row 0 per batch ------------
__global__ void __launch_bounds__(128) cls_kernel()
{
    __shared__ float sims[NN];
    __shared__ float shq[DD];
    __shared__ float red[128];
    const int bh = blockIdx.x;
    const int b = bh / HH, h = bh % HH;
    const int tid = threadIdx.x;

    if (tid < DD)
        shq[tid] = g_qkv[(size_t)(b * NN) * (3 * CC) + h * DD + tid] * SCALE;
    __syncthreads();

    for (int n = tid; n < NN; n += 128) {
        const float* kr = g_qkv + (size_t)(b * NN + n) * (3 * CC) + CC + h * DD;
        float dot = 0.f;
#pragma unroll
        for (int dd = 0; dd < DD; dd++) dot += shq[dd] * kr[dd];
        sims[n] = dot;
    }
    __syncthreads();

    float m = -1e30f;
    for (int n = tid; n < NN; n += 128) m = fmaxf(m, sims[n]);
    red[tid] = m; __syncthreads();
    for (int st = 64; st; st >>= 1) {
        if (tid < st) red[tid] = fmaxf(red[tid], red[tid + st]);
        __syncthreads();
    }
    m = red[0];
    __syncthreads();

    float sm = 0.f;
    for (int n = tid; n < NN; n += 128) {
        float e = __expf(sims[n] - m);
        sims[n] = e;
        sm += e;
    }
    red[tid] = sm; __syncthreads();
    for (int st = 64; st; st >>= 1) {
        if (tid < st) red[tid] += red[tid + st];
        __syncthreads();
    }
    const float inv = 1.f / red[0];
    __syncthreads();

    if (tid < DD) {
        float acc = 0.f;
        for (int n = 0; n < NN; n++)
            acc += sims[n] * g_qkv[(size_t)(b * NN + n) * (3 * CC) + 2 * CC + h * DD + tid];
        g_cat[(size_t)(b * NN) * CC + h * DD + tid] = acc * inv;
    }
}

// ---------------- temporal attention + attn output ------------------------
__global__ void __launch_bounds__(384) temporal_kernel(float* __restrict__ attn_out)
{
    const int m = blockIdx.x;
    const int b = m / SS, s = m % SS;
    const int h = threadIdx.x >> 5;
    const int lane = threadIdx.x & 31;

    const size_t q2off = (size_t)m * CC + h * DD;
    const float qa = g_q2[q2off + lane];
    const float qb = g_q2[q2off + lane + 32];

    float logit[FF];
#pragma unroll
    for (int f = 0; f < FF; f++) {
        size_t k2off = (size_t)(m * FF + f) * CC + h * DD;
        float pr = qa * g_k2[k2off + lane] + qb * g_k2[k2off + lane + 32];
#pragma unroll
        for (int o = 16; o; o >>= 1) pr += __shfl_xor_sync(~0u, pr, o);
        logit[f] = pr * SCALE;
    }
    float mx = logit[0];
#pragma unroll
    for (int f = 1; f < FF; f++) mx = fmaxf(mx, logit[f]);
    float a[FF], sm = 0.f;
#pragma unroll
    for (int f = 0; f < FF; f++) { a[f] = __expf(logit[f] - mx); sm += a[f]; }
    const float inv = 1.f / sm;

    const size_t aoff = ((size_t)(b * HH + h) * SS + s) * FF;
#pragma unroll
    for (int f = 0; f < FF; f++)
        if (lane == f) attn_out[aoff + f] = a[f] * inv;

    float acc1 = 0.f, acc2 = 0.f;
#pragma unroll
    for (int f = 0; f < FF; f++) {
        size_t toff = (size_t)(m * FF + f) * CC + h * DD;
        float w = a[f] * inv;
        acc1 += w * g_traj[toff + lane];
        acc2 += w * g_traj[toff + lane + 32];
    }
    const size_t co = (size_t)(b * NN + 1 + s) * CC + h * DD;
    g_cat[co + lane] = acc1;
    g_cat[co + lane + 32] = acc2;
}

// ---------------- launch ---------------------------------------------------
extern "C" void kernel_launch(void* const* d_in, const int* in_sizes, int n_in,
                              void* d_out, int out_size)
{
    const float* x      = (const float*)d_in[0];
    const float* W_qkv  = (const float*)d_in[1];
    const float* W_pq   = (const float*)d_in[2];
    const float* W_pkv  = (const float*)d_in[3];
    const float* W_proj = (const float*)d_in[4];
    const float* b_proj = (const float*)d_in[5];
    float* out  = (float*)d_out;                       // (B,N,C)
    float* attn = out + (size_t)BB * NN * CC;          // (B,H,S,F)

    float *p_qkv, *p_xdiag, *p_q2, *p_k2, *p_cat, *p_traj;
    cudaGetSymbolAddress((void**)&p_qkv,   g_qkv);
    cudaGetSymbolAddress((void**)&p_traj,  g_traj);
    cudaGetSymbolAddress((void**)&p_xdiag, g_xdiag);
    cudaGetSymbolAddress((void**)&p_q2,    g_q2);
    cudaGetSymbolAddress((void**)&p_k2,    g_k2);
    cudaGetSymbolAddress((void**)&p_cat,   g_cat);

    cudaFuncSetAttribute(space_attn_tc_kernel,
                         cudaFuncAttributeMaxDynamicSharedMemorySize, SP_TOT);
    cudaFuncSetAttribute(tc_gemm_kernel,
                         cudaFuncAttributeMaxDynamicSharedMemorySize, SM_TOT);

    // 0. weight transpose + bf16 split
    transpose_split_kernel<<<dim3(2304 / 32, CC / 32), 256>>>(W_qkv, 3 * CC, 0, WOFF_QKV, 2304);
    transpose_split_kernel<<<dim3(CC / 32, CC / 32), 256>>>(W_pq, CC, 0, WOFF_PQ, CC);
    transpose_split_kernel<<<dim3(CC / 32, CC / 32), 256>>>(W_pkv, 2 * CC, 0, WOFF_PKVK, CC);
    transpose_split_kernel<<<dim3(CC / 32, CC / 32), 256>>>(W_proj, CC, 0, WOFF_PROJ, CC);

    // 1. qkv = x @ W_qkv    (M=3138, N=2304, K=768)
    tc_gemm_kernel<<<dim3((BB * NN + 127) / 128, 2304 / 128), 256, SM_TOT>>>(
        x, WOFF_QKV, nullptr, p_qkv, BB * NN, 3 * CC, CC);
    // 2. cls attention
    cls_kernel<<<BH, 128>>>();
    // 3. space attention (tensor cores) -> g_traj + g_xdiag fused
    space_attn_tc_kernel<<<dim3((SS + QT - 1) / QT, BH), 256, SP_TOT>>>();
    // 4. q2 = x_diag @ W_pq  (M=3136, N=768, K=768)
    tc_gemm_kernel<<<dim3((BB * SS + 127) / 128, CC / 128), 256, SM_TOT>>>(
        p_xdiag, WOFF_PQ, nullptr, p_q2, BB * SS, CC, CC);
    // 5. k2 = traj @ W_pkv[:, :768]  (M=25088, N=768, K=768)
    tc_gemm_kernel<<<dim3((BB * SS * FF + 127) / 128, CC / 128), 256, SM_TOT>>>(
        p_traj, WOFF_PKVK, nullptr, p_k2, BB * SS * FF, CC, CC);
    // 6. temporal attention
    temporal_kernel<<<BB * SS, 384>>>(attn);
    // 7. out = g_cat @ W_proj + b_proj  (M=3138, N=768, K=768)
    tc_gemm_kernel<<<dim3((BB * NN + 127) / 128, CC / 128), 256, SM_TOT>>>(
        p_cat, WOFF_PROJ, b_proj, out, BB * NN, CC, CC);
}

// round 15
// speedup vs baseline: 4.6667x; 1.0629x over previous
#include <cuda_runtime.h>
#include <cuda_bf16.h>
#include <cstdint>
#include <cstddef>

// Problem constants
#define BB 2
#define NN 1569
#define CC 768
#define HH 12
#define DD 64
#define FF 8
#define PP 196
#define SS 1568        // F*P
#define BH 24          // B*H
#define SCALE 0.125f   // d^-0.5

// ---------------- scratch (device globals; no allocation) ----------------
__device__ float g_q2 [(size_t)BB * SS * CC];              // (B,S,C) fp32
__device__ float g_k2 [(size_t)BB * SS * FF * CC];         // (B,S,F,C) fp32

// bf16 hi/lo activation pools
__device__ __nv_bfloat16 g_xb    [2][(size_t)BB * NN * CC];       // x split
__device__ __nv_bfloat16 g_qkvb  [2][(size_t)BB * NN * 3 * CC];   // qkv split
__device__ __nv_bfloat16 g_trajb [2][(size_t)BB * SS * FF * CC];  // traj split
__device__ __nv_bfloat16 g_xdiagb[2][(size_t)BB * SS * CC];       // x_diag split
__device__ __nv_bfloat16 g_catb  [2][(size_t)BB * NN * CC];       // concat split

// bf16 split weight pool (transposed [N,K] K-major): qkv|pq|pkv_k|proj
#define WPOOL_ROWS 4608
__device__ __nv_bfloat16 g_wb[2][(size_t)WPOOL_ROWS * CC];
#define WOFF_QKV  0
#define WOFF_PQ   (2304 * CC)
#define WOFF_PKVK (3072 * CC)
#define WOFF_PROJ (3840 * CC)

// ====================== PTX helpers (compute_103-safe) =====================
__device__ __forceinline__ uint32_t smem_to_u32(const void* p) {
    uint32_t a;
    asm("{ .reg .u64 t; cvta.to.shared.u64 t, %1; cvt.u32.u64 %0, t; }" : "=r"(a) : "l"(p));
    return a;
}
__device__ __forceinline__ void ldsm_x4(uint32_t& d0, uint32_t& d1, uint32_t& d2, uint32_t& d3,
                                        uint32_t a) {
    asm volatile("ldmatrix.sync.aligned.m8n8.x4.shared.b16 {%0,%1,%2,%3}, [%4];"
                 : "=r"(d0), "=r"(d1), "=r"(d2), "=r"(d3) : "r"(a));
}
__device__ __forceinline__ void ldsm_x2(uint32_t& d0, uint32_t& d1, uint32_t a) {
    asm volatile("ldmatrix.sync.aligned.m8n8.x2.shared.b16 {%0,%1}, [%2];"
                 : "=r"(d0), "=r"(d1) : "r"(a));
}
__device__ __forceinline__ void ldsm_x2_t(uint32_t& d0, uint32_t& d1, uint32_t a) {
    asm volatile("ldmatrix.sync.aligned.m8n8.x2.trans.shared.b16 {%0,%1}, [%2];"
                 : "=r"(d0), "=r"(d1) : "r"(a));
}
__device__ __forceinline__ void mma_bf16(float* c, const uint32_t* a, const uint32_t* b) {
    asm volatile(
        "mma.sync.aligned.m16n8k16.row.col.f32.bf16.bf16.f32 "
        "{%0,%1,%2,%3}, {%4,%5,%6,%7}, {%8,%9}, {%0,%1,%2,%3};"
        : "+f"(c[0]), "+f"(c[1]), "+f"(c[2]), "+f"(c[3])
        : "r"(a[0]), "r"(a[1]), "r"(a[2]), "r"(a[3]), "r"(b[0]), "r"(b[1]));
}
// 16B async copy, zero-fill when !ok (src must still be a valid address)
__device__ __forceinline__ void cp16(uint32_t dst, const void* src, bool ok) {
    asm volatile("cp.async.cg.shared.global [%0], [%1], 16, %2;"
                 :: "r"(dst), "l"(src), "r"(ok ? 16 : 0) : "memory");
}
#define CP_COMMIT() asm volatile("cp.async.commit_group;" ::: "memory")
#define CP_WAIT0()  asm volatile("cp.async.wait_group 0;" ::: "memory")
#define CP_WAIT1()  asm volatile("cp.async.wait_group 1;" ::: "memory")

// pack two floats into bf16x2 hi + residual lo
__device__ __forceinline__ void split2(float x, float y, uint32_t& hi, uint32_t& lo) {
    __nv_bfloat162 h = __floats2bfloat162_rn(x, y);
    float rx = x - __bfloat162float(h.x);
    float ry = y - __bfloat162float(h.y);
    __nv_bfloat162 l = __floats2bfloat162_rn(rx, ry);
    hi = *(uint32_t*)&h;
    lo = *(uint32_t*)&l;
}
// fast 2^t on the FMA pipe (t <= ~0, clamped), err ~2e-6 rel
__device__ __forceinline__ float fexp2(float t) {
    t = fmaxf(t, -120.f);
    float tr = t + 12582912.0f;
    int ki = __float_as_int(tr) - 0x4B400000;
    float f = t - (tr - 12582912.0f);
    float p = 1.3333558e-3f;
    p = fmaf(p, f, 9.6181291e-3f);
    p = fmaf(p, f, 5.5504109e-2f);
    p = fmaf(p, f, 2.4022651e-1f);
    p = fmaf(p, f, 6.9314718e-1f);
    p = fmaf(p, f, 1.0f);
    return p * __int_as_float((ki + 127) << 23);
}

// ============ transpose + bf16-split of a weight block =====================
__global__ void __launch_bounds__(256) transpose_split_kernel(
    const float* __restrict__ in, int ldb, int c0, size_t woff, int Nt)
{
    __shared__ float tile[32][33];
    const int nb = blockIdx.x * 32, kb = blockIdx.y * 32;
    const int tx = threadIdx.x & 31, ty = threadIdx.x >> 5;
#pragma unroll
    for (int i = 0; i < 32; i += 8)
        tile[ty + i][tx] = in[(size_t)(kb + ty + i) * ldb + c0 + nb + tx];
    __syncthreads();
#pragma unroll
    for (int i = 0; i < 32; i += 8) {
        float v = tile[tx][ty + i];
        __nv_bfloat16 hi = __float2bfloat16(v);
        __nv_bfloat16 lo = __float2bfloat16(v - __bfloat162float(hi));
        size_t o = woff + (size_t)(nb + ty + i) * CC + kb + tx;
        g_wb[0][o] = hi;
        g_wb[1][o] = lo;
    }
}

// ============ elementwise bf16 split (for x) ===============================
__global__ void __launch_bounds__(256) split_kernel(
    const float* __restrict__ in, __nv_bfloat16* __restrict__ oh,
    __nv_bfloat16* __restrict__ ol, int n4)
{
    int i = blockIdx.x * 256 + threadIdx.x;
    if (i >= n4) return;
    float4 v = *(const float4*)(in + (size_t)i * 4);
    uint32_t h01, l01, h23, l23;
    split2(v.x, v.y, h01, l01);
    split2(v.z, v.w, h23, l23);
    *(uint2*)(oh + (size_t)i * 4) = make_uint2(h01, h23);
    *(uint2*)(ol + (size_t)i * 4) = make_uint2(l01, l23);
}

// ================== bf16x3 HMMA GEMM, cp.async double-buffered =============
// C[M,N] = (Ahi+Alo)[M,K] @ Bt[N,K]^T (weight pool woff), out fp32 [+bias]
// or split bf16 hi/lo pools (Chi/Clo). Tile 128x128, K-chunk 64, 256 thr.
#define GS_AHI 0
#define GS_ALO 16384
#define GS_BHI 32768
#define GS_BLO 49152
#define GS_STAGE 65536
#define GS_TOT 131072

__device__ __forceinline__ void gemm_issue(
    uint32_t sb, const __nv_bfloat16* __restrict__ Ahi,
    const __nv_bfloat16* __restrict__ Alo,
    const __nv_bfloat16* __restrict__ Bh, const __nv_bfloat16* __restrict__ Bl,
    int m0, int n0, int k0, int M, int K, int tid)
{
#pragma unroll
    for (int it = 0; it < 4; it++) {
        int idx = it * 256 + tid;          // 1024 chunks of 16B
        int r = idx >> 3, ch = idx & 7;
        uint32_t off = (uint32_t)(r * 128 + ((ch ^ (r & 7)) << 4));
        int row = m0 + r;
        bool ok = row < M;
        size_t so = (size_t)(ok ? row : 0) * K + k0 + ch * 8;
        cp16(sb + GS_AHI + off, Ahi + so, ok);
        cp16(sb + GS_ALO + off, Alo + so, ok);
        size_t bo = (size_t)(n0 + r) * K + k0 + ch * 8;
        cp16(sb + GS_BHI + off, Bh + bo, true);
        cp16(sb + GS_BLO + off, Bl + bo, true);
    }
    CP_COMMIT();
}

__global__ void __launch_bounds__(256) tc_gemm_kernel(
    const __nv_bfloat16* __restrict__ Ahi, const __nv_bfloat16* __restrict__ Alo,
    size_t woff, const float* __restrict__ bias,
    float* __restrict__ Cf, __nv_bfloat16* __restrict__ Chi,
    __nv_bfloat16* __restrict__ Clo, int M, int N, int K)
{
    extern __shared__ char smem[];
    const uint32_t smu = smem_to_u32(smem);
    const int tid = threadIdx.x, wid = tid >> 5, lane = tid & 31;
    const int wm = wid >> 2, wn = wid & 3;
    const int m0 = blockIdx.x * 128, n0 = blockIdx.y * 128;
    const __nv_bfloat16* Bh = &g_wb[0][woff];
    const __nv_bfloat16* Bl = &g_wb[1][woff];

    float acc[4][4][4];
#pragma unroll
    for (int i = 0; i < 4; i++)
#pragma unroll
        for (int j = 0; j < 4; j++)
#pragma unroll
            for (int t = 0; t < 4; t++) acc[i][j][t] = 0.f;

    const int nch = K >> 6;
    gemm_issue(smu, Ahi, Alo, Bh, Bl, m0, n0, 0, M, K, tid);

    for (int kc = 0; kc < nch; kc++) {
        if (kc + 1 < nch) {
            gemm_issue(smu + ((kc + 1) & 1) * GS_STAGE, Ahi, Alo, Bh, Bl,
                       m0, n0, (kc + 1) << 6, M, K, tid);
            CP_WAIT1();
        } else {
            CP_WAIT0();
        }
        __syncthreads();
        const uint32_t sb = smu + (kc & 1) * GS_STAGE;

#pragma unroll
        for (int ks = 0; ks < 4; ks++) {
            uint32_t ahi[4][4], alo[4][4], bhi[4][2], blo[4][2];
#pragma unroll
            for (int i = 0; i < 4; i++) {
                int mi = lane >> 3;
                int row = wm * 64 + i * 16 + ((mi & 1) << 3) + (lane & 7);
                int kch = ks * 2 + (mi >> 1);
                uint32_t off = (uint32_t)(row * 128 + ((kch ^ (row & 7)) << 4));
                ldsm_x4(ahi[i][0], ahi[i][1], ahi[i][2], ahi[i][3], sb + GS_AHI + off);
                ldsm_x4(alo[i][0], alo[i][1], alo[i][2], alo[i][3], sb + GS_ALO + off);
            }
#pragma unroll
            for (int j = 0; j < 4; j++) {
                int l = lane & 15;
                int n = wn * 32 + j * 8 + (l & 7);
                int kch = ks * 2 + (l >> 3);
                uint32_t off = (uint32_t)(n * 128 + ((kch ^ (n & 7)) << 4));
                ldsm_x2(bhi[j][0], bhi[j][1], sb + GS_BHI + off);
                ldsm_x2(blo[j][0], blo[j][1], sb + GS_BLO + off);
            }
#pragma unroll
            for (int i = 0; i < 4; i++)
#pragma unroll
                for (int j = 0; j < 4; j++) {
                    mma_bf16(acc[i][j], ahi[i], bhi[j]);
                    mma_bf16(acc[i][j], ahi[i], blo[j]);
                    mma_bf16(acc[i][j], alo[i], bhi[j]);
                }
        }
        __syncthreads();
    }

    // ---- epilogue: fp32 (+bias) or split bf16 pools ----
#pragma unroll
    for (int i = 0; i < 4; i++) {
        int rbase = m0 + wm * 64 + i * 16 + (lane >> 2);
#pragma unroll
        for (int j = 0; j < 4; j++) {
            int col = n0 + wn * 32 + j * 8 + (lane & 3) * 2;
            if (Cf) {
                float b0 = bias ? bias[col] : 0.f;
                float b1 = bias ? bias[col + 1] : 0.f;
                if (rbase < M)
                    *(float2*)(Cf + (size_t)rbase * N + col) =
                        make_float2(acc[i][j][0] + b0, acc[i][j][1] + b1);
                if (rbase + 8 < M)
                    *(float2*)(Cf + (size_t)(rbase + 8) * N + col) =
                        make_float2(acc[i][j][2] + b0, acc[i][j][3] + b1);
            } else {
                uint32_t hi, lo;
                if (rbase < M) {
                    split2(acc[i][j][0], acc[i][j][1], hi, lo);
                    size_t o = (size_t)rbase * N + col;
                    *(uint32_t*)(Chi + o) = hi;
                    *(uint32_t*)(Clo + o) = lo;
                }
                if (rbase + 8 < M) {
                    split2(acc[i][j][2], acc[i][j][3], hi, lo);
                    size_t o = (size_t)(rbase + 8) * N + col;
                    *(uint32_t*)(Chi + o) = hi;
                    *(uint32_t*)(Clo + o) = lo;
                }
            }
        }
    }
}

// ============ tensor-core flash space attention + fused xdiag ==============
#define QT 128
#define EC2 0.18033688011112042f   // SCALE * log2(e)
#define SP_QHI 0
#define SP_QLO 16384
#define SP_KHI 32768
#define SP_KLO 59392
#define SP_VHI 86016
#define SP_VLO 112640
#define SP_TOT 139264

__global__ void __launch_bounds__(256) space_attn_tc_kernel()
{
    extern __shared__ char smem[];
    const uint32_t smu = smem_to_u32(smem);
    const int tid = threadIdx.x, wid = tid >> 5, lane = tid & 31;
    const int bh = blockIdx.y;
    const int b = bh / HH, h = bh % HH;
    const int s0 = blockIdx.x * QT;

    // ---- Q tile: cp.async from pre-split pools (128 x 64) ----
#pragma unroll
    for (int it = 0; it < 4; it++) {
        int idx = it * 256 + tid;          // 1024 chunks
        int r = idx >> 3, ch = idx & 7;
        int tq = s0 + r;
        bool ok = tq < SS;
        size_t so = (size_t)(b * NN + 1 + (ok ? tq : 0)) * (3 * CC) + h * DD + ch * 8;
        uint32_t off = (uint32_t)(r * 128 + ((ch ^ (r & 7)) << 4));
        cp16(smu + SP_QHI + off, &g_qkvb[0][so], ok);
        cp16(smu + SP_QLO + off, &g_qkvb[1][so], ok);
    }
    CP_COMMIT();

    for (int f = 0; f < FF; f++) {
        __syncthreads();   // prior frame's smem reads done
        // ---- K_f, V_f: cp.async (208 x 64; rows >=196 zero-filled) ----
#pragma unroll
        for (int it = 0; it < 7; it++) {
            int idx = it * 256 + tid;      // 1664 chunks
            if (idx < 1664) {
                int r = idx >> 3, ch = idx & 7;
                bool ok = r < PP;
                size_t tokso = (size_t)(b * NN + 1 + f * PP + (ok ? r : 0)) * (3 * CC)
                             + h * DD + ch * 8;
                uint32_t off = (uint32_t)(r * 128 + ((ch ^ (r & 7)) << 4));
                cp16(smu + SP_KHI + off, &g_qkvb[0][tokso + CC], ok);
                cp16(smu + SP_KLO + off, &g_qkvb[1][tokso + CC], ok);
                cp16(smu + SP_VHI + off, &g_qkvb[0][tokso + 2 * CC], ok);
                cp16(smu + SP_VLO + off, &g_qkvb[1][tokso + 2 * CC], ok);
            }
        }
        CP_COMMIT();
        CP_WAIT0();
        __syncthreads();

        // ---- QK^T (bf16x3) -> S[26][4] fp32 ----
        float S[26][4];
#pragma unroll
        for (int nt = 0; nt < 26; nt++) {
            S[nt][0] = 0.f; S[nt][1] = 0.f; S[nt][2] = 0.f; S[nt][3] = 0.f;
        }
#pragma unroll 1
        for (int pass = 0; pass < 3; pass++) {
            const int pA = (pass == 2) ? SP_QLO : SP_QHI;
            const int pB = (pass == 1) ? SP_KLO : SP_KHI;
#pragma unroll 1
            for (int kc = 0; kc < 4; kc++) {
                uint32_t a[4];
                int mi = lane >> 3;
                int arow = wid * 16 + ((mi & 1) << 3) + (lane & 7);
                int akch = kc * 2 + (mi >> 1);
                ldsm_x4(a[0], a[1], a[2], a[3],
                        smu + pA + (uint32_t)(arow * 128 + ((akch ^ (arow & 7)) << 4)));
                int l = lane & 15;
                int bkch = kc * 2 + (l >> 3);
#pragma unroll
                for (int nt = 0; nt < 26; nt++) {
                    uint32_t bb[2];
                    int brow = nt * 8 + (l & 7);
                    ldsm_x2(bb[0], bb[1],
                            smu + pB + (uint32_t)(brow * 128 + ((bkch ^ (brow & 7)) << 4)));
                    mma_bf16(S[nt], a, bb);
                }
            }
        }

        // ---- softmax (poly exp on FMA pipe) ----
        const int colbase = 2 * (lane & 3);
        float m0 = -1e30f, m1 = -1e30f;
#pragma unroll
        for (int nt = 0; nt < 26; nt++) {
            if (nt * 8 + colbase < PP) {
                m0 = fmaxf(m0, fmaxf(S[nt][0], S[nt][1]));
                m1 = fmaxf(m1, fmaxf(S[nt][2], S[nt][3]));
            }
        }
        m0 = fmaxf(m0, __shfl_xor_sync(~0u, m0, 1));
        m0 = fmaxf(m0, __shfl_xor_sync(~0u, m0, 2));
        m1 = fmaxf(m1, __shfl_xor_sync(~0u, m1, 1));
        m1 = fmaxf(m1, __shfl_xor_sync(~0u, m1, 2));
        const float mc0 = m0 * EC2, mc1 = m1 * EC2;
        float sum0 = 0.f, sum1 = 0.f;
#pragma unroll
        for (int nt = 0; nt < 26; nt++) {
            if (nt * 8 + colbase < PP) {
                S[nt][0] = fexp2(fmaf(S[nt][0], EC2, -mc0));
                S[nt][1] = fexp2(fmaf(S[nt][1], EC2, -mc0));
                S[nt][2] = fexp2(fmaf(S[nt][2], EC2, -mc1));
                S[nt][3] = fexp2(fmaf(S[nt][3], EC2, -mc1));
                sum0 += S[nt][0] + S[nt][1];
                sum1 += S[nt][2] + S[nt][3];
            } else {
                S[nt][0] = 0.f; S[nt][1] = 0.f; S[nt][2] = 0.f; S[nt][3] = 0.f;
            }
        }
        sum0 += __shfl_xor_sync(~0u, sum0, 1);
        sum0 += __shfl_xor_sync(~0u, sum0, 2);
        sum1 += __shfl_xor_sync(~0u, sum1, 1);
        sum1 += __shfl_xor_sync(~0u, sum1, 2);
        const float inv0 = 1.f / sum0, inv1 = 1.f / sum1;

        // ---- O = P V_f (P reg-resident, bf16x3) ----
        float O[8][4];
#pragma unroll
        for (int nt2 = 0; nt2 < 8; nt2++) {
            O[nt2][0] = 0.f; O[nt2][1] = 0.f; O[nt2][2] = 0.f; O[nt2][3] = 0.f;
        }
#pragma unroll
        for (int kc2 = 0; kc2 < 13; kc2++) {
            uint32_t ah[4], al[4];
            split2(S[2 * kc2][0] * inv0, S[2 * kc2][1] * inv0, ah[0], al[0]);
            split2(S[2 * kc2][2] * inv1, S[2 * kc2][3] * inv1, ah[1], al[1]);
            split2(S[2 * kc2 + 1][0] * inv0, S[2 * kc2 + 1][1] * inv0, ah[2], al[2]);
            split2(S[2 * kc2 + 1][2] * inv1, S[2 * kc2 + 1][3] * inv1, ah[3], al[3]);
            int vrow = kc2 * 16 + (lane & 15);
#pragma unroll
            for (int nt2 = 0; nt2 < 8; nt2++) {
                uint32_t bh2[2], bl2[2];
                uint32_t off = (uint32_t)(vrow * 128 + ((nt2 ^ (vrow & 7)) << 4));
                ldsm_x2_t(bh2[0], bh2[1], smu + SP_VHI + off);
                ldsm_x2_t(bl2[0], bl2[1], smu + SP_VLO + off);
                mma_bf16(O[nt2], ah, bh2);
                mma_bf16(O[nt2], ah, bl2);
                mma_bf16(O[nt2], al, bh2);
            }
        }

        // ---- write O split (+ fused xdiag split) ----
        const int r0 = s0 + wid * 16 + (lane >> 2);
        const int r1 = r0 + 8;
#pragma unroll
        for (int nt2 = 0; nt2 < 8; nt2++) {
            int col = nt2 * 8 + 2 * (lane & 3);
            uint32_t hi, lo;
            if (r0 < SS) {
                split2(O[nt2][0], O[nt2][1], hi, lo);
                size_t o = ((size_t)((b * SS + r0) * FF + f)) * CC + h * DD + col;
                *(uint32_t*)(&g_trajb[0][o]) = hi;
                *(uint32_t*)(&g_trajb[1][o]) = lo;
                if (r0 / PP == f) {
                    size_t od = (size_t)(b * SS + r0) * CC + h * DD + col;
                    *(uint32_t*)(&g_xdiagb[0][od]) = hi;
                    *(uint32_t*)(&g_xdiagb[1][od]) = lo;
                }
            }
            if (r1 < SS) {
                split2(O[nt2][2], O[nt2][3], hi, lo);
                size_t o = ((size_t)((b * SS + r1) * FF + f)) * CC + h * DD + col;
                *(uint32_t*)(&g_trajb[0][o]) = hi;
                *(uint32_t*)(&g_trajb[1][o]) = lo;
                if (r1 / PP == f) {
                    size_t od = (size_t)(b * SS + r1) * CC + h * DD + col;
                    *(uint32_t*)(&g_xdiagb[0][od]) = hi;
                    *(uint32_t*)(&g_xdiagb[1][od]) = lo;
                }
            }
        }
    }
}

// ---------------- cls-token attention -> g_catb row b*NN ------------------
__global__ void __launch_bounds__(128) cls_kernel()
{
    __shared__ float sims[NN];
    __shared__ float shq[DD];
    __shared__ float red[128];
    const int bh = blockIdx.x;
    const int b = bh / HH, h = bh % HH;
    const int tid = threadIdx.x;

    if (tid < DD) {
        size_t o = (size_t)(b * NN) * (3 * CC) + h * DD + tid;
        shq[tid] = (__bfloat162float(g_qkvb[0][o]) + __bfloat162float(g_qkvb[1][o])) * SCALE;
    }
    __syncthreads();

    for (int n = tid; n < NN; n += 128) {
        size_t o = (size_t)(b * NN + n) * (3 * CC) + CC + h * DD;
        float dot = 0.f;
#pragma unroll
        for (int dd = 0; dd < DD; dd++)
            dot += shq[dd] * (__bfloat162float(g_qkvb[0][o + dd]) + __bfloat162float(g_qkvb[1][o + dd]));
        sims[n] = dot;
    }
    __syncthreads();

    float m = -1e30f;
    for (int n = tid; n < NN; n += 128) m = fmaxf(m, sims[n]);
    red[tid] = m; __syncthreads();
    for (int st = 64; st; st >>= 1) {
        if (tid < st) red[tid] = fmaxf(red[tid], red[tid + st]);
        __syncthreads();
    }
    m = red[0];
    __syncthreads();

    float sm = 0.f;
    for (int n = tid; n < NN; n += 128) {
        float e = __expf(sims[n] - m);
        sims[n] = e;
        sm += e;
    }
    red[tid] = sm; __syncthreads();
    for (int st = 64; st; st >>= 1) {
        if (tid < st) red[tid] += red[tid + st];
        __syncthreads();
    }
    const float inv = 1.f / red[0];
    __syncthreads();

    if (tid < DD) {
        float acc = 0.f;
        for (int n = 0; n < NN; n++) {
            size_t o = (size_t)(b * NN + n) * (3 * CC) + 2 * CC + h * DD + tid;
            acc += sims[n] * (__bfloat162float(g_qkvb[0][o]) + __bfloat162float(g_qkvb[1][o]));
        }
        acc *= inv;
        __nv_bfloat16 hi = __float2bfloat16(acc);
        __nv_bfloat16 lo = __float2bfloat16(acc - __bfloat162float(hi));
        size_t co = (size_t)(b * NN) * CC + h * DD + tid;
        g_catb[0][co] = hi;
        g_catb[1][co] = lo;
    }
}

// ---------------- temporal attention + attn output ------------------------
__global__ void __launch_bounds__(384) temporal_kernel(float* __restrict__ attn_out)
{
    const int m = blockIdx.x;
    const int b = m / SS, s = m % SS;
    const int h = threadIdx.x >> 5;
    const int lane = threadIdx.x & 31;

    const size_t q2off = (size_t)m * CC + h * DD;
    const float qa = g_q2[q2off + lane];
    const float qb = g_q2[q2off + lane + 32];

    float logit[FF];
#pragma unroll
    for (int f = 0; f < FF; f++) {
        size_t k2off = (size_t)(m * FF + f) * CC + h * DD;
        float pr = qa * g_k2[k2off + lane] + qb * g_k2[k2off + lane + 32];
#pragma unroll
        for (int o = 16; o; o >>= 1) pr += __shfl_xor_sync(~0u, pr, o);
        logit[f] = pr * SCALE;
    }
    float mx = logit[0];
#pragma unroll
    for (int f = 1; f < FF; f++) mx = fmaxf(mx, logit[f]);
    float a[FF], sm = 0.f;
#pragma unroll
    for (int f = 0; f < FF; f++) { a[f] = __expf(logit[f] - mx); sm += a[f]; }
    const float inv = 1.f / sm;

    const size_t aoff = ((size_t)(b * HH + h) * SS + s) * FF;
#pragma unroll
    for (int f = 0; f < FF; f++)
        if (lane == f) attn_out[aoff + f] = a[f] * inv;

    float acc1 = 0.f, acc2 = 0.f;
#pragma unroll
    for (int f = 0; f < FF; f++) {
        size_t toff = (size_t)(m * FF + f) * CC + h * DD;
        float w = a[f] * inv;
        acc1 += w * (__bfloat162float(g_trajb[0][toff + lane]) +
                     __bfloat162float(g_trajb[1][toff + lane]));
        acc2 += w * (__bfloat162float(g_trajb[0][toff + lane + 32]) +
                     __bfloat162float(g_trajb[1][toff + lane + 32]));
    }
    const size_t co = (size_t)(b * NN + 1 + s) * CC + h * DD;
    {
        __nv_bfloat16 h1 = __float2bfloat16(acc1);
        g_catb[0][co + lane] = h1;
        g_catb[1][co + lane] = __float2bfloat16(acc1 - __bfloat162float(h1));
        __nv_bfloat16 h2 = __float2bfloat16(acc2);
        g_catb[0][co + lane + 32] = h2;
        g_catb[1][co + lane + 32] = __float2bfloat16(acc2 - __bfloat162float(h2));
    }
}

// ---------------- launch ---------------------------------------------------
extern "C" void kernel_launch(void* const* d_in, const int* in_sizes, int n_in,
                              void* d_out, int out_size)
{
    const float* x      = (const float*)d_in[0];
    const float* W_qkv  = (const float*)d_in[1];
    const float* W_pq   = (const float*)d_in[2];
    const float* W_pkv  = (const float*)d_in[3];
    const float* W_proj = (const float*)d_in[4];
    const float* b_proj = (const float*)d_in[5];
    float* out  = (float*)d_out;                       // (B,N,C)
    float* attn = out + (size_t)BB * NN * CC;          // (B,H,S,F)

    float *p_q2, *p_k2;
    cudaGetSymbolAddress((void**)&p_q2, g_q2);
    cudaGetSymbolAddress((void**)&p_k2, g_k2);
    __nv_bfloat16 *p_xb, *p_qkvb, *p_trajb, *p_xdiagb, *p_catb;
    cudaGetSymbolAddress((void**)&p_xb,     g_xb);
    cudaGetSymbolAddress((void**)&p_qkvb,   g_qkvb);
    cudaGetSymbolAddress((void**)&p_trajb,  g_trajb);
    cudaGetSymbolAddress((void**)&p_xdiagb, g_xdiagb);
    cudaGetSymbolAddress((void**)&p_catb,   g_catb);
    const size_t XBN    = (size_t)BB * NN * CC;
    const size_t QKVBN  = (size_t)BB * NN * 3 * CC;
    const size_t TRAJBN = (size_t)BB * SS * FF * CC;
    const size_t XDN    = (size_t)BB * SS * CC;
    const size_t CATBN  = (size_t)BB * NN * CC;

    cudaFuncSetAttribute(space_attn_tc_kernel,
                         cudaFuncAttributeMaxDynamicSharedMemorySize, SP_TOT);
    cudaFuncSetAttribute(tc_gemm_kernel,
                         cudaFuncAttributeMaxDynamicSharedMemorySize, GS_TOT);

    // 0. weight transpose + bf16 split; x elementwise split
    transpose_split_kernel<<<dim3(2304 / 32, CC / 32), 256>>>(W_qkv, 3 * CC, 0, WOFF_QKV, 2304);
    transpose_split_kernel<<<dim3(CC / 32, CC / 32), 256>>>(W_pq, CC, 0, WOFF_PQ, CC);
    transpose_split_kernel<<<dim3(CC / 32, CC / 32), 256>>>(W_pkv, 2 * CC, 0, WOFF_PKVK, CC);
    transpose_split_kernel<<<dim3(CC / 32, CC / 32), 256>>>(W_proj, CC, 0, WOFF_PROJ, CC);
    {
        int n4 = (int)(XBN / 4);
        split_kernel<<<(n4 + 255) / 256, 256>>>(x, p_xb, p_xb + XBN, n4);
    }

    // 1. qkv = x @ W_qkv -> split pools (M=3138, N=2304, K=768)
    tc_gemm_kernel<<<dim3((BB * NN + 127) / 128, 2304 / 128), 256, GS_TOT>>>(
        p_xb, p_xb + XBN, WOFF_QKV, nullptr, nullptr,
        p_qkvb, p_qkvb + QKVBN, BB * NN, 3 * CC, CC);
    // 2. cls attention -> g_catb row b*NN
    cls_kernel<<<BH, 128>>>();
    // 3. space attention -> g_trajb + g_xdiagb (split, fused)
    space_attn_tc_kernel<<<dim3((SS + QT - 1) / QT, BH), 256, SP_TOT>>>();
    // 4. q2 = x_diag @ W_pq -> fp32 (M=3136)
    tc_gemm_kernel<<<dim3((BB * SS + 127) / 128, CC / 128), 256, GS_TOT>>>(
        p_xdiagb, p_xdiagb + XDN, WOFF_PQ, nullptr, p_q2,
        nullptr, nullptr, BB * SS, CC, CC);
    // 5. k2 = traj @ W_pkv[:, :768] -> fp32 (M=25088)
    tc_gemm_kernel<<<dim3((BB * SS * FF + 127) / 128, CC / 128), 256, GS_TOT>>>(
        p_trajb, p_trajb + TRAJBN, WOFF_PKVK, nullptr, p_k2,
        nullptr, nullptr, BB * SS * FF, CC, CC);
    // 6. temporal attention -> g_catb rows, attn -> d_out tail
    temporal_kernel<<<BB * SS, 384>>>(attn);
    // 7. out = cat @ W_proj + b_proj -> fp32 d_out (M=3138)
    tc_gemm_kernel<<<dim3((BB * NN + 127) / 128, CC / 128), 256, GS_TOT>>>(
        p_catb, p_catb + CATBN, WOFF_PROJ, b_proj, out,
        nullptr, nullptr, BB * NN, CC, CC);
}

// round 17
// speedup vs baseline: 5.5957x; 1.1991x over previous
#include <cuda_runtime.h>
#include <cuda_bf16.h>
#include <cstdint>
#include <cstddef>

// Problem constants
#define BB 2
#define NN 1569
#define CC 768
#define HH 12
#define DD 64
#define FF 8
#define PP 196
#define SS 1568        // F*P
#define BH 24          // B*H
#define SCALE 0.125f   // d^-0.5

// ---------------- scratch (device globals; no allocation) ----------------
__device__ float g_qt [(size_t)BB * SS * HH * CC];         // (B*S, h, c) fp32

// bf16 hi/lo activation pools
__device__ __nv_bfloat16 g_xb    [2][(size_t)BB * NN * CC];       // x split
__device__ __nv_bfloat16 g_qkvb  [2][(size_t)BB * NN * 3 * CC];   // qkv split
__device__ __nv_bfloat16 g_trajb [2][(size_t)BB * SS * FF * CC];  // traj split
__device__ __nv_bfloat16 g_xdiagb[2][(size_t)BB * SS * CC];       // x_diag split
__device__ __nv_bfloat16 g_q2b   [2][(size_t)BB * SS * CC];       // q2 split
__device__ __nv_bfloat16 g_catb  [2][(size_t)BB * NN * CC];       // concat split

// bf16 split weight pool (transposed [N,K] K-major): qkv|pq|proj
#define WPOOL_ROWS 3840
#define WPOOLN ((size_t)WPOOL_ROWS * CC)
__device__ __nv_bfloat16 g_wb[2][WPOOLN];
#define WOFF_QKV  0
#define WOFF_PQ   (2304 * CC)
#define WOFF_PROJ (3072 * CC)
// raw (untransposed) W_pkv k-half, split bf16: [c][j] j<768
__device__ __nv_bfloat16 g_wqtb[2][(size_t)CC * CC];

// ====================== PTX helpers (compute_103-safe) =====================
__device__ __forceinline__ uint32_t smem_to_u32(const void* p) {
    uint32_t a;
    asm("{ .reg .u64 t; cvta.to.shared.u64 t, %1; cvt.u32.u64 %0, t; }" : "=r"(a) : "l"(p));
    return a;
}
__device__ __forceinline__ void ldsm_x4(uint32_t& d0, uint32_t& d1, uint32_t& d2, uint32_t& d3,
                                        uint32_t a) {
    asm volatile("ldmatrix.sync.aligned.m8n8.x4.shared.b16 {%0,%1,%2,%3}, [%4];"
                 : "=r"(d0), "=r"(d1), "=r"(d2), "=r"(d3) : "r"(a));
}
__device__ __forceinline__ void ldsm_x2(uint32_t& d0, uint32_t& d1, uint32_t a) {
    asm volatile("ldmatrix.sync.aligned.m8n8.x2.shared.b16 {%0,%1}, [%2];"
                 : "=r"(d0), "=r"(d1) : "r"(a));
}
__device__ __forceinline__ void ldsm_x2_t(uint32_t& d0, uint32_t& d1, uint32_t a) {
    asm volatile("ldmatrix.sync.aligned.m8n8.x2.trans.shared.b16 {%0,%1}, [%2];"
                 : "=r"(d0), "=r"(d1) : "r"(a));
}
__device__ __forceinline__ void mma_bf16(float* c, const uint32_t* a, const uint32_t* b) {
    asm volatile(
        "mma.sync.aligned.m16n8k16.row.col.f32.bf16.bf16.f32 "
        "{%0,%1,%2,%3}, {%4,%5,%6,%7}, {%8,%9}, {%0,%1,%2,%3};"
        : "+f"(c[0]), "+f"(c[1]), "+f"(c[2]), "+f"(c[3])
        : "r"(a[0]), "r"(a[1]), "r"(a[2]), "r"(a[3]), "r"(b[0]), "r"(b[1]));
}
// 16B async copy, zero-fill when !ok (src must still be a valid address)
__device__ __forceinline__ void cp16(uint32_t dst, const void* src, bool ok) {
    asm volatile("cp.async.cg.shared.global [%0], [%1], 16, %2;"
                 :: "r"(dst), "l"(src), "r"(ok ? 16 : 0) : "memory");
}
#define CP_COMMIT() asm volatile("cp.async.commit_group;" ::: "memory")
#define CP_WAIT0()  asm volatile("cp.async.wait_group 0;" ::: "memory")
#define CP_WAIT1()  asm volatile("cp.async.wait_group 1;" ::: "memory")

// pack two floats into bf16x2 hi + residual lo
__device__ __forceinline__ void split2(float x, float y, uint32_t& hi, uint32_t& lo) {
    __nv_bfloat162 h = __floats2bfloat162_rn(x, y);
    float rx = x - __bfloat162float(h.x);
    float ry = y - __bfloat162float(h.y);
    __nv_bfloat162 l = __floats2bfloat162_rn(rx, ry);
    hi = *(uint32_t*)&h;
    lo = *(uint32_t*)&l;
}
// fast 2^t on the FMA pipe (t <= ~0, clamped), err ~2e-6 rel
__device__ __forceinline__ float fexp2(float t) {
    t = fmaxf(t, -120.f);
    float tr = t + 12582912.0f;
    int ki = __float_as_int(tr) - 0x4B400000;
    float f = t - (tr - 12582912.0f);
    float p = 1.3333558e-3f;
    p = fmaf(p, f, 9.6181291e-3f);
    p = fmaf(p, f, 5.5504109e-2f);
    p = fmaf(p, f, 2.4022651e-1f);
    p = fmaf(p, f, 6.9314718e-1f);
    p = fmaf(p, f, 1.0f);
    return p * __int_as_float((ki + 127) << 23);
}

// ============ transpose + bf16-split of a weight block =====================
__global__ void __launch_bounds__(256) transpose_split_kernel(
    const float* __restrict__ in, int ldb, size_t woff)
{
    __shared__ float tile[32][33];
    const int nb = blockIdx.x * 32, kb = blockIdx.y * 32;
    const int tx = threadIdx.x & 31, ty = threadIdx.x >> 5;
#pragma unroll
    for (int i = 0; i < 32; i += 8)
        tile[ty + i][tx] = in[(size_t)(kb + ty + i) * ldb + nb + tx];
    __syncthreads();
#pragma unroll
    for (int i = 0; i < 32; i += 8) {
        float v = tile[tx][ty + i];
        __nv_bfloat16 hi = __float2bfloat16(v);
        __nv_bfloat16 lo = __float2bfloat16(v - __bfloat162float(hi));
        size_t o = woff + (size_t)(nb + ty + i) * CC + kb + tx;
        g_wb[0][o] = hi;
        g_wb[1][o] = lo;
    }
}

// ============ elementwise bf16 split ======================================
__global__ void __launch_bounds__(256) split_kernel(
    const float* __restrict__ in, __nv_bfloat16* __restrict__ oh,
    __nv_bfloat16* __restrict__ ol, int n4)
{
    int i = blockIdx.x * 256 + threadIdx.x;
    if (i >= n4) return;
    float4 v = *(const float4*)(in + (size_t)i * 4);
    uint32_t h01, l01, h23, l23;
    split2(v.x, v.y, h01, l01);
    split2(v.z, v.w, h23, l23);
    *(uint2*)(oh + (size_t)i * 4) = make_uint2(h01, h23);
    *(uint2*)(ol + (size_t)i * 4) = make_uint2(l01, l23);
}

// ============ strided row split (W_pkv k-half) =============================
__global__ void __launch_bounds__(256) split_rows_kernel(
    const float* __restrict__ in, int ldin,
    __nv_bfloat16* __restrict__ oh, __nv_bfloat16* __restrict__ ol,
    int rows, int cols)
{
    int i = blockIdx.x * 256 + threadIdx.x;         // over rows*cols/4
    if (i * 4 >= rows * cols) return;
    int r = (i * 4) / cols, c = (i * 4) % cols;
    float4 v = *(const float4*)(in + (size_t)r * ldin + c);
    uint32_t h01, l01, h23, l23;
    split2(v.x, v.y, h01, l01);
    split2(v.z, v.w, h23, l23);
    size_t o = (size_t)r * cols + c;
    *(uint2*)(oh + o) = make_uint2(h01, h23);
    *(uint2*)(ol + o) = make_uint2(l01, l23);
}

// ================== bf16x3 HMMA GEMM, cp.async double-buffered =============
// C[M,*] = (Ahi+Alo)[M,K] @ B[N,K]^T, generalized strides + z-batch offsets.
#define GS_AHI 0
#define GS_ALO 16384
#define GS_BHI 32768
#define GS_BLO 49152
#define GS_STAGE 65536
#define GS_TOT 131072

__device__ __forceinline__ void gemm_issue(
    uint32_t sb, const __nv_bfloat16* __restrict__ Ahi,
    const __nv_bfloat16* __restrict__ Alo,
    const __nv_bfloat16* __restrict__ Bh, const __nv_bfloat16* __restrict__ Bl,
    int m0, int n0, int k0, int M, int lda, int ldb, int tid)
{
#pragma unroll
    for (int it = 0; it < 4; it++) {
        int idx = it * 256 + tid;          // 1024 chunks of 16B
        int r = idx >> 3, ch = idx & 7;
        uint32_t off = (uint32_t)(r * 128 + ((ch ^ (r & 7)) << 4));
        int row = m0 + r;
        bool ok = row < M;
        size_t so = (size_t)(ok ? row : 0) * lda + k0 + ch * 8;
        cp16(sb + GS_AHI + off, Ahi + so, ok);
        cp16(sb + GS_ALO + off, Alo + so, ok);
        size_t bo = (size_t)(n0 + r) * ldb + k0 + ch * 8;
        cp16(sb + GS_BHI + off, Bh + bo, true);
        cp16(sb + GS_BLO + off, Bl + bo, true);
    }
    CP_COMMIT();
}

__global__ void __launch_bounds__(256) tc_gemm_kernel(
    const __nv_bfloat16* __restrict__ Ahi, const __nv_bfloat16* __restrict__ Alo,
    int lda, int za,
    const __nv_bfloat16* __restrict__ Bh, const __nv_bfloat16* __restrict__ Bl,
    int ldb, int zb,
    const float* __restrict__ bias,
    float* __restrict__ Cf, __nv_bfloat16* __restrict__ Chi,
    __nv_bfloat16* __restrict__ Clo, int ldc, int zc, int M, int K)
{
    extern __shared__ char smem[];
    const uint32_t smu = smem_to_u32(smem);
    const int tid = threadIdx.x, wid = tid >> 5, lane = tid & 31;
    const int wm = wid >> 2, wn = wid & 3;
    const int m0 = blockIdx.x * 128, n0 = blockIdx.y * 128;
    const int z = blockIdx.z;
    Ahi += (size_t)z * za;
    Alo += (size_t)z * za;
    Bh  += (size_t)z * zb;
    Bl  += (size_t)z * zb;
    const size_t zcoff = (size_t)z * zc;

    float acc[4][4][4];
#pragma unroll
    for (int i = 0; i < 4; i++)
#pragma unroll
        for (int j = 0; j < 4; j++)
#pragma unroll
            for (int t = 0; t < 4; t++) acc[i][j][t] = 0.f;

    const int nch = K >> 6;
    gemm_issue(smu, Ahi, Alo, Bh, Bl, m0, n0, 0, M, lda, ldb, tid);

    for (int kc = 0; kc < nch; kc++) {
        if (kc + 1 < nch) {
            gemm_issue(smu + ((kc + 1) & 1) * GS_STAGE, Ahi, Alo, Bh, Bl,
                       m0, n0, (kc + 1) << 6, M, lda, ldb, tid);
            CP_WAIT1();
        } else {
            CP_WAIT0();
        }
        __syncthreads();
        const uint32_t sb = smu + (kc & 1) * GS_STAGE;

#pragma unroll
        for (int ks = 0; ks < 4; ks++) {
            uint32_t ahi[4][4], alo[4][4], bhi[4][2], blo[4][2];
#pragma unroll
            for (int i = 0; i < 4; i++) {
                int mi = lane >> 3;
                int row = wm * 64 + i * 16 + ((mi & 1) << 3) + (lane & 7);
                int kch = ks * 2 + (mi >> 1);
                uint32_t off = (uint32_t)(row * 128 + ((kch ^ (row & 7)) << 4));
                ldsm_x4(ahi[i][0], ahi[i][1], ahi[i][2], ahi[i][3], sb + GS_AHI + off);
                ldsm_x4(alo[i][0], alo[i][1], alo[i][2], alo[i][3], sb + GS_ALO + off);
            }
#pragma unroll
            for (int j = 0; j < 4; j++) {
                int l = lane & 15;
                int n = wn * 32 + j * 8 + (l & 7);
                int kch = ks * 2 + (l >> 3);
                uint32_t off = (uint32_t)(n * 128 + ((kch ^ (n & 7)) << 4));
                ldsm_x2(bhi[j][0], bhi[j][1], sb + GS_BHI + off);
                ldsm_x2(blo[j][0], blo[j][1], sb + GS_BLO + off);
            }
#pragma unroll
            for (int i = 0; i < 4; i++)
#pragma unroll
                for (int j = 0; j < 4; j++) {
                    mma_bf16(acc[i][j], ahi[i], bhi[j]);
                    mma_bf16(acc[i][j], ahi[i], blo[j]);
                    mma_bf16(acc[i][j], alo[i], bhi[j]);
                }
        }
        __syncthreads();
    }

    // ---- epilogue ----
#pragma unroll
    for (int i = 0; i < 4; i++) {
        int rbase = m0 + wm * 64 + i * 16 + (lane >> 2);
#pragma unroll
        for (int j = 0; j < 4; j++) {
            int col = n0 + wn * 32 + j * 8 + (lane & 3) * 2;
            if (Cf) {
                float b0 = bias ? bias[col] : 0.f;
                float b1 = bias ? bias[col + 1] : 0.f;
                if (rbase < M)
                    *(float2*)(Cf + zcoff + (size_t)rbase * ldc + col) =
                        make_float2(acc[i][j][0] + b0, acc[i][j][1] + b1);
                if (rbase + 8 < M)
                    *(float2*)(Cf + zcoff + (size_t)(rbase + 8) * ldc + col) =
                        make_float2(acc[i][j][2] + b0, acc[i][j][3] + b1);
            } else {
                uint32_t hi, lo;
                if (rbase < M) {
                    split2(acc[i][j][0], acc[i][j][1], hi, lo);
                    size_t o = zcoff + (size_t)rbase * ldc + col;
                    *(uint32_t*)(Chi + o) = hi;
                    *(uint32_t*)(Clo + o) = lo;
                }
                if (rbase + 8 < M) {
                    split2(acc[i][j][2], acc[i][j][3], hi, lo);
                    size_t o = zcoff + (size_t)(rbase + 8) * ldc + col;
                    *(uint32_t*)(Chi + o) = hi;
                    *(uint32_t*)(Clo + o) = lo;
                }
            }
        }
    }
}

// ============ tensor-core flash space attention + fused xdiag ==============
#define QT 128
#define EC2 0.18033688011112042f   // SCALE * log2(e)
#define SP_QHI 0
#define SP_QLO 16384
#define SP_KHI 32768
#define SP_KLO 59392
#define SP_VHI 86016
#define SP_VLO 112640
#define SP_TOT 139264

__global__ void __launch_bounds__(256) space_attn_tc_kernel()
{
    extern __shared__ char smem[];
    const uint32_t smu = smem_to_u32(smem);
    const int tid = threadIdx.x, wid = tid >> 5, lane = tid & 31;
    const int bh = blockIdx.y;
    const int b = bh / HH, h = bh % HH;
    const int s0 = blockIdx.x * QT;

    // ---- Q tile: cp.async from pre-split pools (128 x 64) ----
#pragma unroll
    for (int it = 0; it < 4; it++) {
        int idx = it * 256 + tid;          // 1024 chunks
        int r = idx >> 3, ch = idx & 7;
        int tq = s0 + r;
        bool ok = tq < SS;
        size_t so = (size_t)(b * NN + 1 + (ok ? tq : 0)) * (3 * CC) + h * DD + ch * 8;
        uint32_t off = (uint32_t)(r * 128 + ((ch ^ (r & 7)) << 4));
        cp16(smu + SP_QHI + off, &g_qkvb[0][so], ok);
        cp16(smu + SP_QLO + off, &g_qkvb[1][so], ok);
    }
    CP_COMMIT();

    for (int f = 0; f < FF; f++) {
        __syncthreads();   // prior frame's smem reads done
        // ---- K_f, V_f: cp.async (208 x 64; rows >=196 zero-filled) ----
#pragma unroll
        for (int it = 0; it < 7; it++) {
            int idx = it * 256 + tid;      // 1664 chunks
            if (idx < 1664) {
                int r = idx >> 3, ch = idx & 7;
                bool ok = r < PP;
                size_t tokso = (size_t)(b * NN + 1 + f * PP + (ok ? r : 0)) * (3 * CC)
                             + h * DD + ch * 8;
                uint32_t off = (uint32_t)(r * 128 + ((ch ^ (r & 7)) << 4));
                cp16(smu + SP_KHI + off, &g_qkvb[0][tokso + CC], ok);
                cp16(smu + SP_KLO + off, &g_qkvb[1][tokso + CC], ok);
                cp16(smu + SP_VHI + off, &g_qkvb[0][tokso + 2 * CC], ok);
                cp16(smu + SP_VLO + off, &g_qkvb[1][tokso + 2 * CC], ok);
            }
        }
        CP_COMMIT();
        CP_WAIT0();
        __syncthreads();

        // ---- QK^T (bf16x3) -> S[26][4] fp32 ----
        float S[26][4];
#pragma unroll
        for (int nt = 0; nt < 26; nt++) {
            S[nt][0] = 0.f; S[nt][1] = 0.f; S[nt][2] = 0.f; S[nt][3] = 0.f;
        }
#pragma unroll 1
        for (int pass = 0; pass < 3; pass++) {
            const int pA = (pass == 2) ? SP_QLO : SP_QHI;
            const int pB = (pass == 1) ? SP_KLO : SP_KHI;
#pragma unroll 1
            for (int kc = 0; kc < 4; kc++) {
                uint32_t a[4];
                int mi = lane >> 3;
                int arow = wid * 16 + ((mi & 1) << 3) + (lane & 7);
                int akch = kc * 2 + (mi >> 1);
                ldsm_x4(a[0], a[1], a[2], a[3],
                        smu + pA + (uint32_t)(arow * 128 + ((akch ^ (arow & 7)) << 4)));
                int l = lane & 15;
                int bkch = kc * 2 + (l >> 3);
#pragma unroll
                for (int nt = 0; nt < 26; nt++) {
                    uint32_t bb[2];
                    int brow = nt * 8 + (l & 7);
                    ldsm_x2(bb[0], bb[1],
                            smu + pB + (uint32_t)(brow * 128 + ((bkch ^ (brow & 7)) << 4)));
                    mma_bf16(S[nt], a, bb);
                }
            }
        }

        // ---- softmax (poly exp on FMA pipe) ----
        const int colbase = 2 * (lane & 3);
        float m0 = -1e30f, m1 = -1e30f;
#pragma unroll
        for (int nt = 0; nt < 26; nt++) {
            if (nt * 8 + colbase < PP) {
                m0 = fmaxf(m0, fmaxf(S[nt][0], S[nt][1]));
                m1 = fmaxf(m1, fmaxf(S[nt][2], S[nt][3]));
            }
        }
        m0 = fmaxf(m0, __shfl_xor_sync(~0u, m0, 1));
        m0 = fmaxf(m0, __shfl_xor_sync(~0u, m0, 2));
        m1 = fmaxf(m1, __shfl_xor_sync(~0u, m1, 1));
        m1 = fmaxf(m1, __shfl_xor_sync(~0u, m1, 2));
        const float mc0 = m0 * EC2, mc1 = m1 * EC2;
        float sum0 = 0.f, sum1 = 0.f;
#pragma unroll
        for (int nt = 0; nt < 26; nt++) {
            if (nt * 8 + colbase < PP) {
                S[nt][0] = fexp2(fmaf(S[nt][0], EC2, -mc0));
                S[nt][1] = fexp2(fmaf(S[nt][1], EC2, -mc0));
                S[nt][2] = fexp2(fmaf(S[nt][2], EC2, -mc1));
                S[nt][3] = fexp2(fmaf(S[nt][3], EC2, -mc1));
                sum0 += S[nt][0] + S[nt][1];
                sum1 += S[nt][2] + S[nt][3];
            } else {
                S[nt][0] = 0.f; S[nt][1] = 0.f; S[nt][2] = 0.f; S[nt][3] = 0.f;
            }
        }
        sum0 += __shfl_xor_sync(~0u, sum0, 1);
        sum0 += __shfl_xor_sync(~0u, sum0, 2);
        sum1 += __shfl_xor_sync(~0u, sum1, 1);
        sum1 += __shfl_xor_sync(~0u, sum1, 2);
        const float inv0 = 1.f / sum0, inv1 = 1.f / sum1;

        // ---- O = P V_f (P reg-resident, bf16x3) ----
        float O[8][4];
#pragma unroll
        for (int nt2 = 0; nt2 < 8; nt2++) {
            O[nt2][0] = 0.f; O[nt2][1] = 0.f; O[nt2][2] = 0.f; O[nt2][3] = 0.f;
        }
#pragma unroll
        for (int kc2 = 0; kc2 < 13; kc2++) {
            uint32_t ah[4], al[4];
            split2(S[2 * kc2][0] * inv0, S[2 * kc2][1] * inv0, ah[0], al[0]);
            split2(S[2 * kc2][2] * inv1, S[2 * kc2][3] * inv1, ah[1], al[1]);
            split2(S[2 * kc2 + 1][0] * inv0, S[2 * kc2 + 1][1] * inv0, ah[2], al[2]);
            split2(S[2 * kc2 + 1][2] * inv1, S[2 * kc2 + 1][3] * inv1, ah[3], al[3]);
            int vrow = kc2 * 16 + (lane & 15);
#pragma unroll
            for (int nt2 = 0; nt2 < 8; nt2++) {
                uint32_t bh2[2], bl2[2];
                uint32_t off = (uint32_t)(vrow * 128 + ((nt2 ^ (vrow & 7)) << 4));
                ldsm_x2_t(bh2[0], bh2[1], smu + SP_VHI + off);
                ldsm_x2_t(bl2[0], bl2[1], smu + SP_VLO + off);
                mma_bf16(O[nt2], ah, bh2);
                mma_bf16(O[nt2], ah, bl2);
                mma_bf16(O[nt2], al, bh2);
            }
        }

        // ---- write O split (+ fused xdiag split) ----
        const int r0 = s0 + wid * 16 + (lane >> 2);
        const int r1 = r0 + 8;
#pragma unroll
        for (int nt2 = 0; nt2 < 8; nt2++) {
            int col = nt2 * 8 + 2 * (lane & 3);
            uint32_t hi, lo;
            if (r0 < SS) {
                split2(O[nt2][0], O[nt2][1], hi, lo);
                size_t o = ((size_t)((b * SS + r0) * FF + f)) * CC + h * DD + col;
                *(uint32_t*)(&g_trajb[0][o]) = hi;
                *(uint32_t*)(&g_trajb[1][o]) = lo;
                if (r0 / PP == f) {
                    size_t od = (size_t)(b * SS + r0) * CC + h * DD + col;
                    *(uint32_t*)(&g_xdiagb[0][od]) = hi;
                    *(uint32_t*)(&g_xdiagb[1][od]) = lo;
                }
            }
            if (r1 < SS) {
                split2(O[nt2][2], O[nt2][3], hi, lo);
                size_t o = ((size_t)((b * SS + r1) * FF + f)) * CC + h * DD + col;
                *(uint32_t*)(&g_trajb[0][o]) = hi;
                *(uint32_t*)(&g_trajb[1][o]) = lo;
                if (r1 / PP == f) {
                    size_t od = (size_t)(b * SS + r1) * CC + h * DD + col;
                    *(uint32_t*)(&g_xdiagb[0][od]) = hi;
                    *(uint32_t*)(&g_xdiagb[1][od]) = lo;
                }
            }
        }
    }
}

// ---------------- cls-token attention -> g_catb row b*NN ------------------
__global__ void __launch_bounds__(128) cls_kernel()
{
    __shared__ float sims[NN];
    __shared__ float shq[DD];
    __shared__ float red[128];
    const int bh = blockIdx.x;
    const int b = bh / HH, h = bh % HH;
    const int tid = threadIdx.x;

    if (tid < DD) {
        size_t o = (size_t)(b * NN) * (3 * CC) + h * DD + tid;
        shq[tid] = (__bfloat162float(g_qkvb[0][o]) + __bfloat162float(g_qkvb[1][o])) * SCALE;
    }
    __syncthreads();

    for (int n = tid; n < NN; n += 128) {
        size_t o = (size_t)(b * NN + n) * (3 * CC) + CC + h * DD;
        float dot = 0.f;
#pragma unroll
        for (int dd = 0; dd < DD; dd++)
            dot += shq[dd] * (__bfloat162float(g_qkvb[0][o + dd]) + __bfloat162float(g_qkvb[1][o + dd]));
        sims[n] = dot;
    }
    __syncthreads();

    float m = -1e30f;
    for (int n = tid; n < NN; n += 128) m = fmaxf(m, sims[n]);
    red[tid] = m; __syncthreads();
    for (int st = 64; st; st >>= 1) {
        if (tid < st) red[tid] = fmaxf(red[tid], red[tid + st]);
        __syncthreads();
    }
    m = red[0];
    __syncthreads();

    float sm = 0.f;
    for (int n = tid; n < NN; n += 128) {
        float e = __expf(sims[n] - m);
        sims[n] = e;
        sm += e;
    }
    red[tid] = sm; __syncthreads();
    for (int st = 64; st; st >>= 1) {
        if (tid < st) red[tid] += red[tid + st];
        __syncthreads();
    }
    const float inv = 1.f / red[0];
    __syncthreads();

    if (tid < DD) {
        float acc = 0.f;
        for (int n = 0; n < NN; n++) {
            size_t o = (size_t)(b * NN + n) * (3 * CC) + 2 * CC + h * DD + tid;
            acc += sims[n] * (__bfloat162float(g_qkvb[0][o]) + __bfloat162float(g_qkvb[1][o]));
        }
        acc *= inv;
        __nv_bfloat16 hi = __float2bfloat16(acc);
        __nv_bfloat16 lo = __float2bfloat16(acc - __bfloat162float(hi));
        size_t co = (size_t)(b * NN) * CC + h * DD + tid;
        g_catb[0][co] = hi;
        g_catb[1][co] = lo;
    }
}

// ---------------- temporal attention via qt (k2 eliminated) ----------------
// logit[s,f,h] = SCALE * sum_c qt[s,h,c] * traj[s,f,c]
// grid: B*S blocks, 384 threads (12 warps, warp = head)
__global__ void __launch_bounds__(384) temporal_kernel(float* __restrict__ attn_out)
{
    __shared__ float trajs[FF * CC];      // 24 KB fp32
    const int m = blockIdx.x;             // b*S + s
    const int b = m / SS, s = m % SS;
    const int tid = threadIdx.x;
    const int h = tid >> 5;
    const int lane = tid & 31;

    // stage traj[s, :, :] reconstructed fp32
    const size_t tbase = (size_t)m * FF * CC;
    for (int g = tid; g < (FF * CC) / 4; g += 384) {
        uint2 vh = *(const uint2*)(&g_trajb[0][tbase + g * 4]);
        uint2 vl = *(const uint2*)(&g_trajb[1][tbase + g * 4]);
        __nv_bfloat162 h01 = *(__nv_bfloat162*)&vh.x;
        __nv_bfloat162 h23 = *(__nv_bfloat162*)&vh.y;
        __nv_bfloat162 l01 = *(__nv_bfloat162*)&vl.x;
        __nv_bfloat162 l23 = *(__nv_bfloat162*)&vl.y;
        trajs[g * 4 + 0] = __bfloat162float(h01.x) + __bfloat162float(l01.x);
        trajs[g * 4 + 1] = __bfloat162float(h01.y) + __bfloat162float(l01.y);
        trajs[g * 4 + 2] = __bfloat162float(h23.x) + __bfloat162float(l23.x);
        trajs[g * 4 + 3] = __bfloat162float(h23.y) + __bfloat162float(l23.y);
    }
    __syncthreads();

    // logits: each warp owns a head; lanes stride over c
    float lg[FF];
#pragma unroll
    for (int f = 0; f < FF; f++) lg[f] = 0.f;
    const float* qtrow = g_qt + ((size_t)m * HH + h) * CC;
#pragma unroll
    for (int i = 0; i < CC / 32; i++) {
        int c = lane + 32 * i;
        float qv = qtrow[c];
#pragma unroll
        for (int f = 0; f < FF; f++)
            lg[f] = fmaf(qv, trajs[f * CC + c], lg[f]);
    }
#pragma unroll
    for (int f = 0; f < FF; f++) {
#pragma unroll
        for (int o = 16; o; o >>= 1) lg[f] += __shfl_xor_sync(~0u, lg[f], o);
        lg[f] *= SCALE;
    }

    float mx = lg[0];
#pragma unroll
    for (int f = 1; f < FF; f++) mx = fmaxf(mx, lg[f]);
    float a[FF], sm = 0.f;
#pragma unroll
    for (int f = 0; f < FF; f++) { a[f] = __expf(lg[f] - mx); sm += a[f]; }
    const float inv = 1.f / sm;

    const size_t aoff = ((size_t)(b * HH + h) * SS + s) * FF;
#pragma unroll
    for (int f = 0; f < FF; f++)
        if (lane == f) attn_out[aoff + f] = a[f] * inv;

    // out[s,h,d] = sum_f w[f] * traj[s,f,hD+d]
    float acc1 = 0.f, acc2 = 0.f;
#pragma unroll
    for (int f = 0; f < FF; f++) {
        float w = a[f] * inv;
        acc1 = fmaf(w, trajs[f * CC + h * DD + lane], acc1);
        acc2 = fmaf(w, trajs[f * CC + h * DD + lane + 32], acc2);
    }
    const size_t co = (size_t)(b * NN + 1 + s) * CC + h * DD;
    {
        __nv_bfloat16 h1 = __float2bfloat16(acc1);
        g_catb[0][co + lane] = h1;
        g_catb[1][co + lane] = __float2bfloat16(acc1 - __bfloat162float(h1));
        __nv_bfloat16 h2 = __float2bfloat16(acc2);
        g_catb[0][co + lane + 32] = h2;
        g_catb[1][co + lane + 32] = __float2bfloat16(acc2 - __bfloat162float(h2));
    }
}

// ---------------- launch ---------------------------------------------------
extern "C" void kernel_launch(void* const* d_in, const int* in_sizes, int n_in,
                              void* d_out, int out_size)
{
    const float* x      = (const float*)d_in[0];
    const float* W_qkv  = (const float*)d_in[1];
    const float* W_pq   = (const float*)d_in[2];
    const float* W_pkv  = (const float*)d_in[3];
    const float* W_proj = (const float*)d_in[4];
    const float* b_proj = (const float*)d_in[5];
    float* out  = (float*)d_out;                       // (B,N,C)
    float* attn = out + (size_t)BB * NN * CC;          // (B,H,S,F)

    float* p_qt;
    cudaGetSymbolAddress((void**)&p_qt, g_qt);
    __nv_bfloat16 *p_xb, *p_qkvb, *p_trajb, *p_xdiagb, *p_q2b, *p_catb, *p_wb, *p_wqtb;
    cudaGetSymbolAddress((void**)&p_xb,     g_xb);
    cudaGetSymbolAddress((void**)&p_qkvb,   g_qkvb);
    cudaGetSymbolAddress((void**)&p_trajb,  g_trajb);
    cudaGetSymbolAddress((void**)&p_xdiagb, g_xdiagb);
    cudaGetSymbolAddress((void**)&p_q2b,    g_q2b);
    cudaGetSymbolAddress((void**)&p_catb,   g_catb);
    cudaGetSymbolAddress((void**)&p_wb,     g_wb);
    cudaGetSymbolAddress((void**)&p_wqtb,   g_wqtb);
    const size_t XBN    = (size_t)BB * NN * CC;
    const size_t QKVBN  = (size_t)BB * NN * 3 * CC;
    const size_t TRAJBN = (size_t)BB * SS * FF * CC;
    const size_t XDN    = (size_t)BB * SS * CC;
    const size_t Q2N    = (size_t)BB * SS * CC;
    const size_t CATBN  = (size_t)BB * NN * CC;
    const size_t WQTN   = (size_t)CC * CC;

    cudaFuncSetAttribute(space_attn_tc_kernel,
                         cudaFuncAttributeMaxDynamicSharedMemorySize, SP_TOT);
    cudaFuncSetAttribute(tc_gemm_kernel,
                         cudaFuncAttributeMaxDynamicSharedMemorySize, GS_TOT);

    // 0. weight prep
    transpose_split_kernel<<<dim3(2304 / 32, CC / 32), 256>>>(W_qkv, 3 * CC, WOFF_QKV);
    transpose_split_kernel<<<dim3(CC / 32, CC / 32), 256>>>(W_pq, CC, WOFF_PQ);
    transpose_split_kernel<<<dim3(CC / 32, CC / 32), 256>>>(W_proj, CC, WOFF_PROJ);
    split_rows_kernel<<<(CC * CC / 4 + 255) / 256, 256>>>(
        W_pkv, 2 * CC, p_wqtb, p_wqtb + WQTN, CC, CC);
    {
        int n4 = (int)(XBN / 4);
        split_kernel<<<(n4 + 255) / 256, 256>>>(x, p_xb, p_xb + XBN, n4);
    }

    // 1. qkv = x @ W_qkv -> split pools (M=3138, N=2304, K=768)
    tc_gemm_kernel<<<dim3((BB * NN + 127) / 128, 2304 / 128, 1), 256, GS_TOT>>>(
        p_xb, p_xb + XBN, CC, 0,
        p_wb + WOFF_QKV, p_wb + WPOOLN + WOFF_QKV, CC, 0,
        nullptr, nullptr, p_qkvb, p_qkvb + QKVBN, 3 * CC, 0, BB * NN, CC);
    // 2. cls attention -> g_catb row b*NN
    cls_kernel<<<BH, 128>>>();
    // 3. space attention -> g_trajb + g_xdiagb (split, fused)
    space_attn_tc_kernel<<<dim3((SS + QT - 1) / QT, BH), 256, SP_TOT>>>();
    // 4. q2 = x_diag @ W_pq -> split pools (M=3136)
    tc_gemm_kernel<<<dim3((BB * SS + 127) / 128, CC / 128, 1), 256, GS_TOT>>>(
        p_xdiagb, p_xdiagb + XDN, CC, 0,
        p_wb + WOFF_PQ, p_wb + WPOOLN + WOFF_PQ, CC, 0,
        nullptr, nullptr, p_q2b, p_q2b + Q2N, CC, 0, BB * SS, CC);
    // 5. qt_h = q2_h @ Wk_h^T (z-batched per head, K=64) -> fp32
    tc_gemm_kernel<<<dim3((BB * SS + 127) / 128, CC / 128, HH), 256, GS_TOT>>>(
        p_q2b, p_q2b + Q2N, CC, DD,
        p_wqtb, p_wqtb + WQTN, CC, DD,
        nullptr, p_qt, nullptr, nullptr, HH * CC, CC, BB * SS, DD);
    // 6. temporal attention (qt . traj) -> g_catb rows, attn -> d_out tail
    temporal_kernel<<<BB * SS, 384>>>(attn);
    // 7. out = cat @ W_proj + b_proj -> fp32 d_out (M=3138)
    tc_gemm_kernel<<<dim3((BB * NN + 127) / 128, CC / 128, 1), 256, GS_TOT>>>(
        p_catb, p_catb + CATBN, CC, 0,
        p_wb + WOFF_PROJ, p_wb + WPOOLN + WOFF_PROJ, CC, 0,
        b_proj, out, nullptr, nullptr, CC, 0, BB * NN, CC);
}